// round 5
// baseline (speedup 1.0000x reference)
#include <cuda_runtime.h>
#include <cstdint>
#include <math.h>

#define B_   2
#define L_   8192
#define D_   1024
#define H_   16
#define DH_  64
#define M_   266
#define MPAD 272
#define BL   (B_*L_)
#define BH   (B_*H_)

#define SCALE  0.17677669529663687f   /* 1024^-0.25 */
#define SCALE2 0.03125f               /* SCALE^2 */
#define NC     0.061313932f           /* 266^-0.5 */
#define KEPS   1e-4f
#define NSTAB  1e-6f

#define SPLIT 32
#define KVSZ  (BH*M_*65)
#define OUT_CHUNKS 4

// ---------------- device scratch (no mallocs allowed) ----------------
__device__ float g_Qp[BL*D_];
__device__ float g_Kp[BL*D_];
__device__ float g_Vp[BL*D_];
__device__ float g_ctx[BL*D_];
__device__ float g_hk[BH*L_];
__device__ unsigned int g_kstab;
__device__ float g_kv[KVSZ];
__device__ float g_kvpart[(size_t)SPLIT*KVSZ];

// ================= helpers =================
__device__ __forceinline__ uint32_t smem_u32(const void* p) {
    uint32_t a;
    asm("{ .reg .u64 t; cvta.to.shared.u64 t, %1; cvt.u32.u64 %0, t; }" : "=r"(a) : "l"(p));
    return a;
}

// split fp32x4 -> bf16x4 hi + bf16x4 lo (packed as 2x u32 each)
__device__ __forceinline__ void cvt_split(float4 v, uint32_t& h01, uint32_t& h23,
                                          uint32_t& l01, uint32_t& l23) {
    asm("cvt.rn.bf16x2.f32 %0, %1, %2;" : "=r"(h01) : "f"(v.y), "f"(v.x));
    asm("cvt.rn.bf16x2.f32 %0, %1, %2;" : "=r"(h23) : "f"(v.w), "f"(v.z));
    float r0 = v.x - __uint_as_float(h01 << 16);
    float r1 = v.y - __uint_as_float(h01 & 0xffff0000u);
    float r2 = v.z - __uint_as_float(h23 << 16);
    float r3 = v.w - __uint_as_float(h23 & 0xffff0000u);
    asm("cvt.rn.bf16x2.f32 %0, %1, %2;" : "=r"(l01) : "f"(r1), "f"(r0));
    asm("cvt.rn.bf16x2.f32 %0, %1, %2;" : "=r"(l23) : "f"(r3), "f"(r2));
}

#define LDSM_X4(r0, r1, r2, r3, addr)                                        \
    asm volatile("ldmatrix.sync.aligned.m8n8.x4.shared.b16 {%0,%1,%2,%3}, [%4];" \
        : "=r"(r0), "=r"(r1), "=r"(r2), "=r"(r3) : "r"(addr))

#define MMA_BF16(d, a, b0_, b1_)                                             \
    asm volatile("mma.sync.aligned.m16n8k16.row.col.f32.bf16.bf16.f32 "      \
        "{%0,%1,%2,%3}, {%4,%5,%6,%7}, {%8,%9}, {%0,%1,%2,%3};"              \
        : "+f"((d)[0]), "+f"((d)[1]), "+f"((d)[2]), "+f"((d)[3])             \
        : "r"((a)[0]), "r"((a)[1]), "r"((a)[2]), "r"((a)[3]),                \
          "r"(b0_), "r"(b1_))

// ================= bf16x3 mma.sync GEMM: C[16384,1024] = A @ W^T + bias =================
// CTA tile 128x128, K-chunk 32, 8 warps (2x4), warp tile 64x32.
#define AST 40   /* padded smem row stride in bf16 elements (80B) */

__global__ __launch_bounds__(256, 2) void gemm_mma(const float* __restrict__ A,
                                                   const float* __restrict__ W,
                                                   const float* __restrict__ bias,
                                                   float* __restrict__ C) {
    __shared__ uint16_t sAh[128 * AST];
    __shared__ uint16_t sAl[128 * AST];
    __shared__ uint16_t sBh[128 * AST];
    __shared__ uint16_t sBl[128 * AST];

    const int tid  = threadIdx.x;
    const int lane = tid & 31;
    const int wid  = tid >> 5;
    const int wm   = wid & 1;    // 0..1 -> 64-row slice
    const int wn   = wid >> 1;   // 0..3 -> 32-col slice

    const size_t mbase = (size_t)blockIdx.y * 128;
    const size_t nbase = (size_t)blockIdx.x * 128;
    const float* Ab = A + mbase * D_;
    const float* Wb = W + nbase * D_;

    const uint32_t aH = smem_u32(sAh), aL = smem_u32(sAl);
    const uint32_t bH = smem_u32(sBh), bL = smem_u32(sBl);

    // ldmatrix per-lane addressing pieces
    const int arow    = lane & 15;
    const int acolsel = (lane >> 4) << 3;               // 0 or 8
    const int brow    = (lane & 7) + ((lane >> 4) << 3); // 0..15
    const int bcolsel = ((lane >> 3) & 1) << 3;          // 0 or 8

    float acc[4][4][4];
    #pragma unroll
    for (int i = 0; i < 4; ++i)
        #pragma unroll
        for (int j = 0; j < 4; ++j)
            #pragma unroll
            for (int k = 0; k < 4; ++k) acc[i][j][k] = 0.f;

    for (int kc = 0; kc < D_ / 32; ++kc) {
        __syncthreads();
        // fill smem: 128 rows x 8 float4 per matrix; 4 float4 per thread each
        #pragma unroll
        for (int j = 0; j < 4; ++j) {
            int fidx = tid + j * 256;     // 0..1023
            int r = fidx >> 3;
            int u = fidx & 7;
            float4 v = *(const float4*)(Ab + (size_t)r * D_ + kc * 32 + u * 4);
            uint32_t h01, h23, l01, l23;
            cvt_split(v, h01, h23, l01, l23);
            *(uint2*)(sAh + r * AST + u * 4) = make_uint2(h01, h23);
            *(uint2*)(sAl + r * AST + u * 4) = make_uint2(l01, l23);
            float4 w = *(const float4*)(Wb + (size_t)r * D_ + kc * 32 + u * 4);
            cvt_split(w, h01, h23, l01, l23);
            *(uint2*)(sBh + r * AST + u * 4) = make_uint2(h01, h23);
            *(uint2*)(sBl + r * AST + u * 4) = make_uint2(l01, l23);
        }
        __syncthreads();

        #pragma unroll
        for (int ks = 0; ks < 2; ++ks) {
            uint32_t af[4][4], bhF[2][4], blF[2][4];
            #pragma unroll
            for (int mt = 0; mt < 4; ++mt) {
                uint32_t off = (uint32_t)(((wm * 64 + mt * 16 + arow) * AST
                                          + ks * 16 + acolsel) * 2);
                LDSM_X4(af[mt][0], af[mt][1], af[mt][2], af[mt][3], aH + off);
            }
            #pragma unroll
            for (int bp = 0; bp < 2; ++bp) {
                uint32_t off = (uint32_t)(((wn * 32 + bp * 16 + brow) * AST
                                          + ks * 16 + bcolsel) * 2);
                LDSM_X4(bhF[bp][0], bhF[bp][1], bhF[bp][2], bhF[bp][3], bH + off);
                LDSM_X4(blF[bp][0], blF[bp][1], blF[bp][2], blF[bp][3], bL + off);
            }
            // pass 1: hi x hi, pass 2: hi x lo
            #pragma unroll
            for (int mt = 0; mt < 4; ++mt) {
                #pragma unroll
                for (int nt = 0; nt < 4; ++nt) {
                    uint32_t b0 = bhF[nt >> 1][(nt & 1) * 2];
                    uint32_t b1 = bhF[nt >> 1][(nt & 1) * 2 + 1];
                    MMA_BF16(acc[mt][nt], af[mt], b0, b1);
                    uint32_t c0 = blF[nt >> 1][(nt & 1) * 2];
                    uint32_t c1 = blF[nt >> 1][(nt & 1) * 2 + 1];
                    MMA_BF16(acc[mt][nt], af[mt], c0, c1);
                }
            }
            // pass 3: lo x hi (reload A frags from lo tile)
            #pragma unroll
            for (int mt = 0; mt < 4; ++mt) {
                uint32_t off = (uint32_t)(((wm * 64 + mt * 16 + arow) * AST
                                          + ks * 16 + acolsel) * 2);
                LDSM_X4(af[mt][0], af[mt][1], af[mt][2], af[mt][3], aL + off);
            }
            #pragma unroll
            for (int mt = 0; mt < 4; ++mt) {
                #pragma unroll
                for (int nt = 0; nt < 4; ++nt) {
                    uint32_t b0 = bhF[nt >> 1][(nt & 1) * 2];
                    uint32_t b1 = bhF[nt >> 1][(nt & 1) * 2 + 1];
                    MMA_BF16(acc[mt][nt], af[mt], b0, b1);
                }
            }
        }
    }

    // epilogue: direct fp32 stores + bias
    #pragma unroll
    for (int mt = 0; mt < 4; ++mt) {
        size_t r0 = mbase + wm * 64 + mt * 16 + (lane >> 2);
        #pragma unroll
        for (int nt = 0; nt < 4; ++nt) {
            int col = (int)nbase + wn * 32 + nt * 8 + 2 * (lane & 3);
            float bx = bias[col], by = bias[col + 1];
            float2 v0 = make_float2(acc[mt][nt][0] + bx, acc[mt][nt][1] + by);
            float2 v1 = make_float2(acc[mt][nt][2] + bx, acc[mt][nt][3] + by);
            *(float2*)(C + r0 * D_ + col)       = v0;
            *(float2*)(C + (r0 + 8) * D_ + col) = v1;
        }
    }
}

// ---------------- init ----------------
__global__ void init_kernel() {
    if (threadIdx.x == 0) g_kstab = 0xFF800000u; // -inf bits
}

// ---------------- h_k per (b,h,l) + global max into g_kstab ----------------
__global__ __launch_bounds__(256) void hk_kernel() {
    int gid = blockIdx.x * 256 + threadIdx.x;   // over BH*L_
    int b = gid / (H_ * L_);
    int rem = gid % (H_ * L_);
    int h = rem / L_;
    int l = rem % L_;
    const float4* row = (const float4*)(g_Kp + (size_t)(b * L_ + l) * D_ + h * DH_);
    float s = 0.f;
    #pragma unroll
    for (int t = 0; t < 16; ++t) {
        float4 v = row[t];
        s = fmaf(v.x, v.x, s); s = fmaf(v.y, v.y, s);
        s = fmaf(v.z, v.z, s); s = fmaf(v.w, v.w, s);
    }
    float hk = -0.5f * SCALE2 * s;   // <= 0 always
    g_hk[gid] = hk;
    float m = hk;
    #pragma unroll
    for (int o = 16; o > 0; o >>= 1) m = fmaxf(m, __shfl_xor_sync(0xffffffffu, m, o));
    __shared__ float wmax[8];
    if ((threadIdx.x & 31) == 0) wmax[threadIdx.x >> 5] = m;
    __syncthreads();
    if (threadIdx.x == 0) {
        float bm = wmax[0];
        #pragma unroll
        for (int w = 1; w < 8; ++w) bm = fmaxf(bm, wmax[w]);
        atomicMin(&g_kstab, __float_as_uint(bm));
    }
}

// proj micro-tile: 2 rows (l0,l1) x 4 features (m0..m0+3), K=64 via float4
__device__ __forceinline__ void proj4x2(const float* __restrict__ sIn,
                                        const float* __restrict__ sWf,
                                        int l0, int l1, int m0, float p[2][4]) {
    const float4* a0 = (const float4*)(sIn + l0 * 68);
    const float4* a1 = (const float4*)(sIn + l1 * 68);
    #pragma unroll
    for (int t = 0; t < 16; ++t) {
        float4 va0 = a0[t], va1 = a1[t];
        #pragma unroll
        for (int j = 0; j < 4; ++j) {
            float4 w = *(const float4*)(sWf + (m0 + j) * 68 + t * 4);
            p[0][j] = fmaf(va0.x, w.x, p[0][j]);
            p[0][j] = fmaf(va0.y, w.y, p[0][j]);
            p[0][j] = fmaf(va0.z, w.z, p[0][j]);
            p[0][j] = fmaf(va0.w, w.w, p[0][j]);
            p[1][j] = fmaf(va1.x, w.x, p[1][j]);
            p[1][j] = fmaf(va1.y, w.y, p[1][j]);
            p[1][j] = fmaf(va1.z, w.z, p[1][j]);
            p[1][j] = fmaf(va1.w, w.w, p[1][j]);
        }
    }
}

// ---------------- kv kernel: partial kv_aug[m, 0..64] per (split,b,h) ----------------
#define KV_SMEM_FLOATS (266*68 + 32*68 + 32*80 + 32*MPAD + 32 + 32)
__global__ __launch_bounds__(256, 1) void kv_kernel(const float* __restrict__ Wf,
                                                    const float* __restrict__ mask) {
    extern __shared__ float sm[];
    float* sWf    = sm;                    // [266][68]
    float* sK     = sWf + 266*68;          // [32][68]
    float* sV     = sK + 32*68;            // [32][80]
    float* kprime = sV + 32*80;            // [32][272]
    float* shk    = kprime + 32*MPAD;      // [32]
    float* smask  = shk + 32;              // [32]

    int tid = threadIdx.x;
    int split = blockIdx.x;
    int h = blockIdx.y, b = blockIdx.z;
    int bh = b * H_ + h;

    for (int idx = tid; idx < M_ * DH_; idx += 256)
        sWf[(idx >> 6) * 68 + (idx & 63)] = Wf[idx];

    float kstab = __uint_as_float(g_kstab);

    const int lt = tid & 15;
    const int mt = tid >> 4;
    const int tx = tid & 15;
    const int ty = tid >> 4;

    float acc[17][5];
    #pragma unroll
    for (int i = 0; i < 17; ++i)
        #pragma unroll
        for (int j = 0; j < 5; ++j) acc[i][j] = 0.f;

    int lstart = split * (L_ / SPLIT);   // 256 rows per block
    for (int c = 0; c < (L_ / SPLIT) / 32; ++c) {
        int lbase = lstart + c * 32;
        __syncthreads();
        for (int idx = tid; idx < 32 * 16; idx += 256) {
            int i = idx >> 4, t = idx & 15;
            float4 v = *(const float4*)(g_Kp + (size_t)(b * L_ + lbase + i) * D_ + h * DH_ + t * 4);
            v.x *= SCALE; v.y *= SCALE; v.z *= SCALE; v.w *= SCALE;
            *(float4*)(sK + i * 68 + t * 4) = v;
        }
        for (int idx = tid; idx < 32 * 20; idx += 256) {
            int i = idx / 20, t = idx % 20;
            float4 v;
            if (t < 16) v = *(const float4*)(g_Vp + (size_t)(b * L_ + lbase + i) * D_ + h * DH_ + t * 4);
            else if (t == 16) v = make_float4(1.f, 0.f, 0.f, 0.f);
            else v = make_float4(0.f, 0.f, 0.f, 0.f);
            *(float4*)(sV + i * 80 + t * 4) = v;
        }
        if (tid < 32) {
            shk[tid]   = g_hk[(size_t)bh * L_ + lbase + tid];
            smask[tid] = mask[(size_t)b * L_ + lbase + tid];
        }
        __syncthreads();
        #pragma unroll
        for (int q = 0; q < 5; ++q) {
            int mq = mt + 16 * q;
            if (mq < 68) {
                int m0 = mq << 2;
                float p[2][4] = {{0,0,0,0},{0,0,0,0}};
                proj4x2(sK, sWf, lt, lt + 16, m0, p);
                float hs0 = shk[lt] - kstab,    hs1 = shk[lt+16] - kstab;
                float mk0 = smask[lt],          mk1 = smask[lt+16];
                float4 o0, o1;
                o0.x = (m0+0 < M_) ? NC*(__expf(p[0][0]+hs0)+KEPS)*mk0 : 0.f;
                o0.y = (m0+1 < M_) ? NC*(__expf(p[0][1]+hs0)+KEPS)*mk0 : 0.f;
                o0.z = (m0+2 < M_) ? NC*(__expf(p[0][2]+hs0)+KEPS)*mk0 : 0.f;
                o0.w = (m0+3 < M_) ? NC*(__expf(p[0][3]+hs0)+KEPS)*mk0 : 0.f;
                o1.x = (m0+0 < M_) ? NC*(__expf(p[1][0]+hs1)+KEPS)*mk1 : 0.f;
                o1.y = (m0+1 < M_) ? NC*(__expf(p[1][1]+hs1)+KEPS)*mk1 : 0.f;
                o1.z = (m0+2 < M_) ? NC*(__expf(p[1][2]+hs1)+KEPS)*mk1 : 0.f;
                o1.w = (m0+3 < M_) ? NC*(__expf(p[1][3]+hs1)+KEPS)*mk1 : 0.f;
                *(float4*)(kprime + lt * MPAD + m0)        = o0;
                *(float4*)(kprime + (lt + 16) * MPAD + m0) = o1;
            }
        }
        __syncthreads();
        #pragma unroll 4
        for (int l = 0; l < 32; ++l) {
            float kp[17], vv[5];
            #pragma unroll
            for (int i = 0; i < 17; ++i) kp[i] = kprime[l * MPAD + ty + 16 * i];
            #pragma unroll
            for (int j = 0; j < 5; ++j) vv[j] = sV[l * 80 + tx + 16 * j];
            #pragma unroll
            for (int i = 0; i < 17; ++i)
                #pragma unroll
                for (int j = 0; j < 5; ++j)
                    acc[i][j] = fmaf(kp[i], vv[j], acc[i][j]);
        }
    }
    size_t base = ((size_t)split * BH + bh) * (M_ * 65);
    #pragma unroll
    for (int i = 0; i < 17; ++i) {
        int m = ty + 16 * i;
        if (m < M_) {
            #pragma unroll
            for (int j = 0; j < 5; ++j) {
                int d = tx + 16 * j;
                if (d < 65) g_kvpart[base + m * 65 + d] = acc[i][j];
            }
        }
    }
}

// ---------------- deterministic reduce of kv partials ----------------
__global__ void kv_reduce() {
    int idx = blockIdx.x * 256 + threadIdx.x;
    if (idx < KVSZ) {
        float s = 0.f;
        #pragma unroll
        for (int p = 0; p < SPLIT; ++p) s += g_kvpart[(size_t)p * KVSZ + idx];
        g_kv[idx] = s;
    }
}

// ---------------- out kernel: ctx = (q' @ kv_aug) / denom, head-merged ----------------
#define OUT_SMEM_FLOATS (266*68 + 32*68 + 32*MPAD + 266*68 + 256 + 32)
__global__ __launch_bounds__(256, 1) void out_kernel(const float* __restrict__ Wf) {
    extern __shared__ float sm[];
    float* sWf    = sm;                    // [266][68]
    float* sQ     = sWf + 266*68;          // [32][68]
    float* qprime = sQ + 32*68;            // [32][272]
    float* skv    = qprime + 32*MPAD;      // [266][68]
    float* sdenp  = skv + 266*68;          // [256]
    float* sden   = sdenp + 256;           // [32]

    int tid = threadIdx.x;
    int h = blockIdx.y, b = blockIdx.z;
    int bh = b * H_ + h;

    for (int idx = tid; idx < M_ * DH_; idx += 256)
        sWf[(idx >> 6) * 68 + (idx & 63)] = Wf[idx];
    const float* kvp = g_kv + (size_t)bh * (M_ * 65);
    for (int idx = tid; idx < M_ * 68; idx += 256) {
        int m = idx / 68, d = idx % 68;
        skv[idx] = (d < 65) ? kvp[m * 65 + d] : 0.f;
    }

    const int lt = tid & 15;
    const int mt = tid >> 4;
    const int tx = tid & 15;
    const int ty = tid >> 4;

    for (int c = 0; c < OUT_CHUNKS; ++c) {
        int lbase = (blockIdx.x * OUT_CHUNKS + c) * 32;
        __syncthreads();
        for (int idx = tid; idx < 32 * 16; idx += 256) {
            int i = idx >> 4, t = idx & 15;
            float4 v = *(const float4*)(g_Qp + (size_t)(b * L_ + lbase + i) * D_ + h * DH_ + t * 4);
            v.x *= SCALE; v.y *= SCALE; v.z *= SCALE; v.w *= SCALE;
            *(float4*)(sQ + i * 68 + t * 4) = v;
        }
        __syncthreads();
        #pragma unroll
        for (int q = 0; q < 5; ++q) {
            int mq = mt + 16 * q;
            if (mq < 68) {
                int m0 = mq << 2;
                float p[2][4] = {{0,0,0,0},{0,0,0,0}};
                proj4x2(sQ, sWf, lt, lt + 16, m0, p);
                float4 o0, o1;
                o0.x = (m0+0 < M_) ? NC*(__expf(p[0][0])+KEPS) : 0.f;
                o0.y = (m0+1 < M_) ? NC*(__expf(p[0][1])+KEPS) : 0.f;
                o0.z = (m0+2 < M_) ? NC*(__expf(p[0][2])+KEPS) : 0.f;
                o0.w = (m0+3 < M_) ? NC*(__expf(p[0][3])+KEPS) : 0.f;
                o1.x = (m0+0 < M_) ? NC*(__expf(p[1][0])+KEPS) : 0.f;
                o1.y = (m0+1 < M_) ? NC*(__expf(p[1][1])+KEPS) : 0.f;
                o1.z = (m0+2 < M_) ? NC*(__expf(p[1][2])+KEPS) : 0.f;
                o1.w = (m0+3 < M_) ? NC*(__expf(p[1][3])+KEPS) : 0.f;
                *(float4*)(qprime + lt * MPAD + m0)        = o0;
                *(float4*)(qprime + (lt + 16) * MPAD + m0) = o1;
            }
        }
        __syncthreads();
        {
            int slice = tid & 7;
            int l = tid >> 3;
            float p = 0.f;
            for (int m = slice; m < M_; m += 8)
                p = fmaf(qprime[l * MPAD + m], skv[m * 68 + 64], p);
            sdenp[tid] = p;
        }
        __syncthreads();
        if (tid < 32) {
            float d = 0.f;
            #pragma unroll
            for (int s = 0; s < 8; ++s) d += sdenp[tid * 8 + s];
            if (fabsf(d) <= NSTAB) d += 2.f * NSTAB;
            sden[tid] = 1.0f / d;
        }
        __syncthreads();
        int l0 = 2 * ty, l1 = 2 * ty + 1;
        float4 a0 = make_float4(0,0,0,0), a1 = make_float4(0,0,0,0);
        #pragma unroll 2
        for (int m = 0; m < M_; ++m) {
            float q0 = qprime[l0 * MPAD + m];
            float q1 = qprime[l1 * MPAD + m];
            float4 kvv = *(const float4*)(skv + m * 68 + tx * 4);
            a0.x = fmaf(q0, kvv.x, a0.x); a0.y = fmaf(q0, kvv.y, a0.y);
            a0.z = fmaf(q0, kvv.z, a0.z); a0.w = fmaf(q0, kvv.w, a0.w);
            a1.x = fmaf(q1, kvv.x, a1.x); a1.y = fmaf(q1, kvv.y, a1.y);
            a1.z = fmaf(q1, kvv.z, a1.z); a1.w = fmaf(q1, kvv.w, a1.w);
        }
        float i0 = sden[l0], i1 = sden[l1];
        a0.x *= i0; a0.y *= i0; a0.z *= i0; a0.w *= i0;
        a1.x *= i1; a1.y *= i1; a1.z *= i1; a1.w *= i1;
        *(float4*)(g_ctx + (size_t)(b * L_ + lbase + l0) * D_ + h * DH_ + tx * 4) = a0;
        *(float4*)(g_ctx + (size_t)(b * L_ + lbase + l1) * D_ + h * DH_ + tx * 4) = a1;
    }
}

// ---------------- launch ----------------
extern "C" void kernel_launch(void* const* d_in, const int* in_sizes, int n_in,
                              void* d_out, int out_size) {
    const float* query = (const float*)d_in[0];
    const float* key   = (const float*)d_in[1];
    const float* value = (const float*)d_in[2];
    const float* mask  = (const float*)d_in[3];
    const float* Wq = (const float*)d_in[4];
    const float* bq = (const float*)d_in[5];
    const float* Wk = (const float*)d_in[6];
    const float* bk = (const float*)d_in[7];
    const float* Wv = (const float*)d_in[8];
    const float* bv = (const float*)d_in[9];
    const float* Wo = (const float*)d_in[10];
    const float* bo = (const float*)d_in[11];
    const float* Wf = (const float*)d_in[12];

    float *Qp, *Kp, *Vp, *ctx;
    cudaGetSymbolAddress((void**)&Qp,  g_Qp);
    cudaGetSymbolAddress((void**)&Kp,  g_Kp);
    cudaGetSymbolAddress((void**)&Vp,  g_Vp);
    cudaGetSymbolAddress((void**)&ctx, g_ctx);

    cudaFuncSetAttribute(kv_kernel,  cudaFuncAttributeMaxDynamicSharedMemorySize,
                         KV_SMEM_FLOATS * (int)sizeof(float));
    cudaFuncSetAttribute(out_kernel, cudaFuncAttributeMaxDynamicSharedMemorySize,
                         OUT_SMEM_FLOATS * (int)sizeof(float));

    init_kernel<<<1, 32>>>();

    dim3 gg(D_ / 128, BL / 128);
    gemm_mma<<<gg, 256>>>(query, Wq, bq, Qp);
    gemm_mma<<<gg, 256>>>(key,   Wk, bk, Kp);
    gemm_mma<<<gg, 256>>>(value, Wv, bv, Vp);

    hk_kernel<<<(BH * L_) / 256, 256>>>();

    kv_kernel<<<dim3(SPLIT, H_, B_), 256, KV_SMEM_FLOATS * sizeof(float)>>>(Wf, mask);
    kv_reduce<<<(KVSZ + 255) / 256, 256>>>();

    out_kernel<<<dim3(L_ / (32 * OUT_CHUNKS), H_, B_), 256,
                 OUT_SMEM_FLOATS * sizeof(float)>>>(Wf);

    gemm_mma<<<gg, 256>>>(ctx, Wo, bo, (float*)d_out);
}

// round 6
// speedup vs baseline: 1.2162x; 1.2162x over previous
#include <cuda_runtime.h>
#include <cstdint>
#include <math.h>

#define B_   2
#define L_   8192
#define D_   1024
#define H_   16
#define DH_  64
#define M_   266
#define MP2  288
#define BL   (B_*L_)
#define BH   (B_*H_)

#define SCALE  0.17677669529663687f
#define SCALE2 0.03125f
#define NC     0.061313932f
#define KEPS   1e-4f
#define NSTAB  1e-6f

#define SPLIT  16
#define KVROW  272
#define KVCOL  72
#define KVSZ2  (BH*KVROW*KVCOL)

// ---------------- device scratch ----------------
__device__ float g_Qp[BL*D_];
__device__ float g_Kp[BL*D_];
__device__ float g_Vp[BL*D_];
__device__ float g_ctx[BL*D_];
__device__ float g_hk[BH*L_];
__device__ unsigned int g_kstab;
__device__ float g_qprime[BH*L_*MP2];
__device__ float g_kprime[BH*L_*MP2];
__device__ float g_kv[KVSZ2];
__device__ float g_kvpart[(size_t)SPLIT*KVSZ2];

// ================= helpers =================
__device__ __forceinline__ uint32_t smem_u32(const void* p) {
    uint32_t a;
    asm("{ .reg .u64 t; cvta.to.shared.u64 t, %1; cvt.u32.u64 %0, t; }" : "=r"(a) : "l"(p));
    return a;
}
__device__ __forceinline__ void cvt_split(float4 v, uint32_t& h01, uint32_t& h23,
                                          uint32_t& l01, uint32_t& l23) {
    asm("cvt.rn.bf16x2.f32 %0, %1, %2;" : "=r"(h01) : "f"(v.y), "f"(v.x));
    asm("cvt.rn.bf16x2.f32 %0, %1, %2;" : "=r"(h23) : "f"(v.w), "f"(v.z));
    float r0 = v.x - __uint_as_float(h01 << 16);
    float r1 = v.y - __uint_as_float(h01 & 0xffff0000u);
    float r2 = v.z - __uint_as_float(h23 << 16);
    float r3 = v.w - __uint_as_float(h23 & 0xffff0000u);
    asm("cvt.rn.bf16x2.f32 %0, %1, %2;" : "=r"(l01) : "f"(r1), "f"(r0));
    asm("cvt.rn.bf16x2.f32 %0, %1, %2;" : "=r"(l23) : "f"(r3), "f"(r2));
}
#define LDSM_X4(r0,r1,r2,r3,addr) \
    asm volatile("ldmatrix.sync.aligned.m8n8.x4.shared.b16 {%0,%1,%2,%3}, [%4];" \
        : "=r"(r0),"=r"(r1),"=r"(r2),"=r"(r3) : "r"(addr))
#define LDSM_X4T(r0,r1,r2,r3,addr) \
    asm volatile("ldmatrix.sync.aligned.m8n8.x4.trans.shared.b16 {%0,%1,%2,%3}, [%4];" \
        : "=r"(r0),"=r"(r1),"=r"(r2),"=r"(r3) : "r"(addr))
#define LDSM_X2T(r0,r1,addr) \
    asm volatile("ldmatrix.sync.aligned.m8n8.x2.trans.shared.b16 {%0,%1}, [%2];" \
        : "=r"(r0),"=r"(r1) : "r"(addr))
#define MMA_BF16(d,a,b0_,b1_) \
    asm volatile("mma.sync.aligned.m16n8k16.row.col.f32.bf16.bf16.f32 " \
        "{%0,%1,%2,%3}, {%4,%5,%6,%7}, {%8,%9}, {%0,%1,%2,%3};" \
        : "+f"((d)[0]),"+f"((d)[1]),"+f"((d)[2]),"+f"((d)[3]) \
        : "r"((a)[0]),"r"((a)[1]),"r"((a)[2]),"r"((a)[3]),"r"(b0_),"r"(b1_))

// ================= bf16x3 dense GEMM (unchanged, proven) =================
#define AST 40
__global__ __launch_bounds__(256, 2) void gemm_mma(const float* __restrict__ A,
                                                   const float* __restrict__ W,
                                                   const float* __restrict__ bias,
                                                   float* __restrict__ C) {
    __shared__ uint16_t sAh[128*AST], sAl[128*AST], sBh[128*AST], sBl[128*AST];
    const int tid = threadIdx.x, lane = tid & 31, wid = tid >> 5;
    const int wm = wid & 1, wn = wid >> 1;
    const size_t mbase = (size_t)blockIdx.y * 128, nbase = (size_t)blockIdx.x * 128;
    const float* Ab = A + mbase * D_;
    const float* Wb = W + nbase * D_;
    const uint32_t aH = smem_u32(sAh), aL = smem_u32(sAl);
    const uint32_t bH = smem_u32(sBh), bL = smem_u32(sBl);
    const int arow = lane & 15, acolsel = (lane >> 4) << 3;
    const int brow = (lane & 7) + ((lane >> 4) << 3), bcolsel = ((lane >> 3) & 1) << 3;
    float acc[4][4][4];
    #pragma unroll
    for (int i = 0; i < 4; ++i)
        #pragma unroll
        for (int j = 0; j < 4; ++j)
            #pragma unroll
            for (int k = 0; k < 4; ++k) acc[i][j][k] = 0.f;
    for (int kc = 0; kc < D_ / 32; ++kc) {
        __syncthreads();
        #pragma unroll
        for (int j = 0; j < 4; ++j) {
            int fidx = tid + j * 256, r = fidx >> 3, u = fidx & 7;
            float4 v = *(const float4*)(Ab + (size_t)r * D_ + kc * 32 + u * 4);
            uint32_t h01, h23, l01, l23;
            cvt_split(v, h01, h23, l01, l23);
            *(uint2*)(sAh + r * AST + u * 4) = make_uint2(h01, h23);
            *(uint2*)(sAl + r * AST + u * 4) = make_uint2(l01, l23);
            float4 w = *(const float4*)(Wb + (size_t)r * D_ + kc * 32 + u * 4);
            cvt_split(w, h01, h23, l01, l23);
            *(uint2*)(sBh + r * AST + u * 4) = make_uint2(h01, h23);
            *(uint2*)(sBl + r * AST + u * 4) = make_uint2(l01, l23);
        }
        __syncthreads();
        #pragma unroll
        for (int ks = 0; ks < 2; ++ks) {
            uint32_t af[4][4], bhF[2][4], blF[2][4];
            #pragma unroll
            for (int mt = 0; mt < 4; ++mt) {
                uint32_t off = (uint32_t)(((wm*64 + mt*16 + arow)*AST + ks*16 + acolsel)*2);
                LDSM_X4(af[mt][0], af[mt][1], af[mt][2], af[mt][3], aH + off);
            }
            #pragma unroll
            for (int bp = 0; bp < 2; ++bp) {
                uint32_t off = (uint32_t)(((wn*32 + bp*16 + brow)*AST + ks*16 + bcolsel)*2);
                LDSM_X4(bhF[bp][0], bhF[bp][1], bhF[bp][2], bhF[bp][3], bH + off);
                LDSM_X4(blF[bp][0], blF[bp][1], blF[bp][2], blF[bp][3], bL + off);
            }
            #pragma unroll
            for (int mt = 0; mt < 4; ++mt)
                #pragma unroll
                for (int nt = 0; nt < 4; ++nt) {
                    MMA_BF16(acc[mt][nt], af[mt], bhF[nt>>1][(nt&1)*2], bhF[nt>>1][(nt&1)*2+1]);
                    MMA_BF16(acc[mt][nt], af[mt], blF[nt>>1][(nt&1)*2], blF[nt>>1][(nt&1)*2+1]);
                }
            #pragma unroll
            for (int mt = 0; mt < 4; ++mt) {
                uint32_t off = (uint32_t)(((wm*64 + mt*16 + arow)*AST + ks*16 + acolsel)*2);
                LDSM_X4(af[mt][0], af[mt][1], af[mt][2], af[mt][3], aL + off);
            }
            #pragma unroll
            for (int mt = 0; mt < 4; ++mt)
                #pragma unroll
                for (int nt = 0; nt < 4; ++nt)
                    MMA_BF16(acc[mt][nt], af[mt], bhF[nt>>1][(nt&1)*2], bhF[nt>>1][(nt&1)*2+1]);
        }
    }
    #pragma unroll
    for (int mt = 0; mt < 4; ++mt) {
        size_t r0 = mbase + wm*64 + mt*16 + (lane >> 2);
        #pragma unroll
        for (int nt = 0; nt < 4; ++nt) {
            int col = (int)nbase + wn*32 + nt*8 + 2*(lane & 3);
            float bx = bias[col], by = bias[col+1];
            *(float2*)(C + r0*D_ + col)     = make_float2(acc[mt][nt][0]+bx, acc[mt][nt][1]+by);
            *(float2*)(C + (r0+8)*D_ + col) = make_float2(acc[mt][nt][2]+bx, acc[mt][nt][3]+by);
        }
    }
}

// ---------------- init / hk ----------------
__global__ void init_kernel() { if (threadIdx.x == 0) g_kstab = 0xFF800000u; }

__global__ __launch_bounds__(256) void hk_kernel() {
    int gid = blockIdx.x * 256 + threadIdx.x;
    int b = gid / (H_*L_), rem = gid % (H_*L_), h = rem / L_, l = rem % L_;
    const float4* row = (const float4*)(g_Kp + (size_t)(b*L_ + l)*D_ + h*DH_);
    float s = 0.f;
    #pragma unroll
    for (int t = 0; t < 16; ++t) {
        float4 v = row[t];
        s = fmaf(v.x,v.x,s); s = fmaf(v.y,v.y,s); s = fmaf(v.z,v.z,s); s = fmaf(v.w,v.w,s);
    }
    float hk = -0.5f * SCALE2 * s;
    g_hk[gid] = hk;
    float m = hk;
    #pragma unroll
    for (int o = 16; o > 0; o >>= 1) m = fmaxf(m, __shfl_xor_sync(0xffffffffu, m, o));
    __shared__ float wmax[8];
    if ((threadIdx.x & 31) == 0) wmax[threadIdx.x >> 5] = m;
    __syncthreads();
    if (threadIdx.x == 0) {
        float bm = wmax[0];
        #pragma unroll
        for (int w = 1; w < 8; ++w) bm = fmaxf(bm, wmax[w]);
        atomicMin(&g_kstab, __float_as_uint(bm));
    }
}

// ================= proj kernel: prime = f(X_head @ Wf^T) =================
// CTA: 64 l-rows x 288 features. 8 warps: wl=wid>>1 (l16 tile), wn=wid&1 (even/odd n16 groups).
#define PJ_WH 0
#define PJ_WL 41472
#define PJ_XH 82944
#define PJ_XL 92160
#define PJ_SMEM 101376
__global__ __launch_bounds__(256, 1) void proj_kernel(const float* __restrict__ X,
                                                      const float* __restrict__ Wf,
                                                      const float* __restrict__ mask,
                                                      float* __restrict__ Out, int isK) {
    extern __shared__ char sm[];
    const uint32_t sb = smem_u32(sm);
    const int tid = threadIdx.x, lane = tid & 31, w = tid >> 5;
    const int h = blockIdx.y, b = blockIdx.z, bh = b*H_ + h;
    const int l0 = blockIdx.x * 64;

    for (int i = tid; i < (PJ_XH) / 4; i += 256) ((uint32_t*)sm)[i] = 0;
    __syncthreads();
    for (int i = tid; i < 266*16; i += 256) {
        int r = i >> 4, u = i & 15;
        float4 v = *(const float4*)(Wf + r*64 + u*4);
        uint32_t h01,h23,l01,l23; cvt_split(v,h01,h23,l01,l23);
        *(uint2*)(sm + PJ_WH + (r*72 + u*4)*2) = make_uint2(h01,h23);
        *(uint2*)(sm + PJ_WL + (r*72 + u*4)*2) = make_uint2(l01,l23);
    }
    for (int i = tid; i < 64*16; i += 256) {
        int r = i >> 4, u = i & 15;
        float4 v = *(const float4*)(X + (size_t)(b*L_ + l0 + r)*D_ + h*64 + u*4);
        v.x*=SCALE; v.y*=SCALE; v.z*=SCALE; v.w*=SCALE;
        uint32_t h01,h23,l01,l23; cvt_split(v,h01,h23,l01,l23);
        *(uint2*)(sm + PJ_XH + (r*72 + u*4)*2) = make_uint2(h01,h23);
        *(uint2*)(sm + PJ_XL + (r*72 + u*4)*2) = make_uint2(l01,l23);
    }
    __syncthreads();

    const int wl = w >> 1, wn = w & 1;
    const int arow = lane & 15, acolsel = (lane >> 4) << 3;
    const int brow = (lane & 7) + ((lane >> 4) << 3), bcolsel = ((lane >> 3) & 1) << 3;

    float acc[18][4];
    #pragma unroll
    for (int i = 0; i < 18; ++i)
        #pragma unroll
        for (int k = 0; k < 4; ++k) acc[i][k] = 0.f;

    #pragma unroll
    for (int ks = 0; ks < 4; ++ks) {
        uint32_t ah[4], al[4];
        uint32_t aoff = (uint32_t)(((wl*16 + arow)*72 + ks*16 + acolsel)*2);
        LDSM_X4(ah[0],ah[1],ah[2],ah[3], sb + PJ_XH + aoff);
        LDSM_X4(al[0],al[1],al[2],al[3], sb + PJ_XL + aoff);
        uint32_t bh9[9][4], bl9[9][4];
        #pragma unroll
        for (int j = 0; j < 9; ++j) {
            int g = wn + 2*j;
            uint32_t off = (uint32_t)(((g*16 + brow)*72 + ks*16 + bcolsel)*2);
            LDSM_X4(bh9[j][0],bh9[j][1],bh9[j][2],bh9[j][3], sb + PJ_WH + off);
            LDSM_X4(bl9[j][0],bl9[j][1],bl9[j][2],bl9[j][3], sb + PJ_WL + off);
        }
        #pragma unroll
        for (int j = 0; j < 9; ++j)
            #pragma unroll
            for (int half = 0; half < 2; ++half) {
                int nt = 2*j + half;
                MMA_BF16(acc[nt], ah, bh9[j][half*2], bh9[j][half*2+1]);
                MMA_BF16(acc[nt], ah, bl9[j][half*2], bl9[j][half*2+1]);
                MMA_BF16(acc[nt], al, bh9[j][half*2], bh9[j][half*2+1]);
            }
    }

    int r0 = wl*16 + (lane >> 2);
    int gl0 = l0 + r0, gl1 = gl0 + 8;
    float add0 = 0.f, add1 = 0.f, mk0 = 1.f, mk1 = 1.f;
    if (isK) {
        float kst = __uint_as_float(g_kstab);
        add0 = g_hk[(size_t)bh*L_ + gl0] - kst;
        add1 = g_hk[(size_t)bh*L_ + gl1] - kst;
        mk0 = mask[b*L_ + gl0];
        mk1 = mask[b*L_ + gl1];
    }
    float* O0 = Out + ((size_t)bh*L_ + gl0)*MP2;
    float* O1 = Out + ((size_t)bh*L_ + gl1)*MP2;
    #pragma unroll
    for (int j = 0; j < 9; ++j)
        #pragma unroll
        for (int half = 0; half < 2; ++half) {
            int nt = 2*j + half;
            int c0 = (wn + 2*j)*16 + half*8 + (lane & 3)*2;
            float2 v0, v1;
            v0.x = (c0   < M_) ? NC*(__expf(acc[nt][0]+add0)+KEPS)*mk0 : 0.f;
            v0.y = (c0+1 < M_) ? NC*(__expf(acc[nt][1]+add0)+KEPS)*mk0 : 0.f;
            v1.x = (c0   < M_) ? NC*(__expf(acc[nt][2]+add1)+KEPS)*mk1 : 0.f;
            v1.y = (c0+1 < M_) ? NC*(__expf(acc[nt][3]+add1)+KEPS)*mk1 : 0.f;
            *(float2*)(O0 + c0) = v0;
            *(float2*)(O1 + c0) = v1;
        }
}

// ================= kv kernel: kvpart = k'^T @ v_aug (split-K over L) =================
#define KST 296
#define KV_KH 0
#define KV_KL 37888
#define KV_VH 75776
#define KV_VL 84992
#define KV_SMEMB 94208
__global__ __launch_bounds__(288, 1) void kv_mma() {
    extern __shared__ char sm[];
    const uint32_t sb = smem_u32(sm);
    const int tid = threadIdx.x, lane = tid & 31, w = tid >> 5;   // w 0..8
    const int split = blockIdx.x, bh = blockIdx.y;
    const int b = bh / H_, h = bh % H_;
    const int arow = lane & 15, acolsel = (lane >> 4) << 3;
    const int brow = (lane & 7) + ((lane >> 4) << 3), bcolsel = ((lane >> 3) & 1) << 3;

    float acc[2][9][4];
    #pragma unroll
    for (int t = 0; t < 2; ++t)
        #pragma unroll
        for (int n = 0; n < 9; ++n)
            #pragma unroll
            for (int k = 0; k < 4; ++k) acc[t][n][k] = 0.f;

    for (int c = 0; c < 8; ++c) {
        int lb = split*512 + c*64;
        __syncthreads();
        for (int i = tid; i < 64*72; i += 288) {
            int r = i / 72, u = i % 72;
            float4 v = *(const float4*)(g_kprime + ((size_t)bh*L_ + lb + r)*MP2 + u*4);
            uint32_t h01,h23,l01,l23; cvt_split(v,h01,h23,l01,l23);
            *(uint2*)(sm + KV_KH + (r*KST + u*4)*2) = make_uint2(h01,h23);
            *(uint2*)(sm + KV_KL + (r*KST + u*4)*2) = make_uint2(l01,l23);
        }
        for (int i = tid; i < 64*18; i += 288) {
            int r = i / 18, u = i % 18;
            float4 v;
            if (u < 16) v = *(const float4*)(g_Vp + (size_t)(b*L_ + lb + r)*D_ + h*64 + u*4);
            else if (u == 16) v = make_float4(1.f, 0.f, 0.f, 0.f);
            else v = make_float4(0.f, 0.f, 0.f, 0.f);
            uint32_t h01,h23,l01,l23; cvt_split(v,h01,h23,l01,l23);
            *(uint2*)(sm + KV_VH + (r*72 + u*4)*2) = make_uint2(h01,h23);
            *(uint2*)(sm + KV_VL + (r*72 + u*4)*2) = make_uint2(l01,l23);
        }
        __syncthreads();
        #pragma unroll
        for (int ks = 0; ks < 4; ++ks) {
            uint32_t ah2[2][4], al2[2][4];
            #pragma unroll
            for (int t = 0; t < 2; ++t) {
                uint32_t off = (uint32_t)(((ks*16 + brow)*KST + (2*w + t)*16 + bcolsel)*2);
                LDSM_X4T(ah2[t][0],ah2[t][1],ah2[t][2],ah2[t][3], sb + KV_KH + off);
                LDSM_X4T(al2[t][0],al2[t][1],al2[t][2],al2[t][3], sb + KV_KL + off);
            }
            uint32_t bh4[4][4], bl4[4][4], bh2[2], bl2[2];
            #pragma unroll
            for (int g = 0; g < 4; ++g) {
                uint32_t off = (uint32_t)(((ks*16 + arow)*72 + g*16 + acolsel)*2);
                LDSM_X4T(bh4[g][0],bh4[g][1],bh4[g][2],bh4[g][3], sb + KV_VH + off);
                LDSM_X4T(bl4[g][0],bl4[g][1],bl4[g][2],bl4[g][3], sb + KV_VL + off);
            }
            uint32_t off2 = (uint32_t)(((ks*16 + (lane & 15))*72 + 64)*2);
            LDSM_X2T(bh2[0], bh2[1], sb + KV_VH + off2);
            LDSM_X2T(bl2[0], bl2[1], sb + KV_VL + off2);
            #pragma unroll
            for (int t = 0; t < 2; ++t)
                #pragma unroll
                for (int nt = 0; nt < 9; ++nt) {
                    uint32_t p0 = (nt < 8) ? bh4[nt>>1][(nt&1)*2]   : bh2[0];
                    uint32_t p1 = (nt < 8) ? bh4[nt>>1][(nt&1)*2+1] : bh2[1];
                    uint32_t q0 = (nt < 8) ? bl4[nt>>1][(nt&1)*2]   : bl2[0];
                    uint32_t q1 = (nt < 8) ? bl4[nt>>1][(nt&1)*2+1] : bl2[1];
                    MMA_BF16(acc[t][nt], ah2[t], p0, p1);
                    MMA_BF16(acc[t][nt], ah2[t], q0, q1);
                    MMA_BF16(acc[t][nt], al2[t], p0, p1);
                }
        }
    }
    float* base = g_kvpart + (size_t)(split*BH + bh)*KVROW*KVCOL;
    #pragma unroll
    for (int t = 0; t < 2; ++t) {
        int m0 = w*32 + t*16;
        if (m0 < KVROW) {
            int r0 = m0 + (lane >> 2);
            #pragma unroll
            for (int nt = 0; nt < 9; ++nt) {
                int c0 = nt*8 + (lane & 3)*2;
                *(float2*)(base + (size_t)r0*KVCOL + c0)     = make_float2(acc[t][nt][0], acc[t][nt][1]);
                *(float2*)(base + (size_t)(r0+8)*KVCOL + c0) = make_float2(acc[t][nt][2], acc[t][nt][3]);
            }
        }
    }
}

__global__ void kv_reduce() {
    int idx = blockIdx.x * 256 + threadIdx.x;
    if (idx < KVSZ2) {
        float s = 0.f;
        #pragma unroll
        for (int p = 0; p < SPLIT; ++p) s += g_kvpart[(size_t)p*KVSZ2 + idx];
        g_kv[idx] = s;
    }
}

// ================= out kernel: ctx = (q' @ kv) / denom =================
#define OU_QH 0
#define OU_QL 18432
#define OU_KH 36864
#define OU_KL 78336
#define OU_SMEM 119808
__global__ __launch_bounds__(256, 1) void out_mma(const float* __restrict__ dummy) {
    extern __shared__ char sm[];
    const uint32_t sb = smem_u32(sm);
    const int tid = threadIdx.x, lane = tid & 31, w = tid >> 5;
    const int h = blockIdx.y, b = blockIdx.z, bh = b*H_ + h;
    const int l0 = blockIdx.x * 128;
    const int arow = lane & 15, acolsel = (lane >> 4) << 3;

    for (int i = tid; i < (OU_SMEM - OU_KH) / 4; i += 256) ((uint32_t*)(sm + OU_KH))[i] = 0;
    __syncthreads();
    for (int i = tid; i < KVROW*18; i += 256) {
        int r = i / 18, u = i % 18;
        float4 v = *(const float4*)(g_kv + ((size_t)bh*KVROW + r)*KVCOL + u*4);
        uint32_t h01,h23,l01,l23; cvt_split(v,h01,h23,l01,l23);
        *(uint2*)(sm + OU_KH + (r*72 + u*4)*2) = make_uint2(h01,h23);
        *(uint2*)(sm + OU_KL + (r*72 + u*4)*2) = make_uint2(l01,l23);
    }

    float acc[9][4];
    #pragma unroll
    for (int n = 0; n < 9; ++n)
        #pragma unroll
        for (int k = 0; k < 4; ++k) acc[n][k] = 0.f;

    for (int mc = 0; mc < 5; ++mc) {
        int kst = (mc < 4) ? 4 : 2;
        int nf4 = kst * 4;
        __syncthreads();
        for (int i = tid; i < 128*nf4; i += 256) {
            int r = i / nf4, u = i % nf4;
            float4 v = *(const float4*)(g_qprime + ((size_t)bh*L_ + l0 + r)*MP2 + mc*64 + u*4);
            uint32_t h01,h23,l01,l23; cvt_split(v,h01,h23,l01,l23);
            *(uint2*)(sm + OU_QH + (r*72 + u*4)*2) = make_uint2(h01,h23);
            *(uint2*)(sm + OU_QL + (r*72 + u*4)*2) = make_uint2(l01,l23);
        }
        __syncthreads();
        for (int ks = 0; ks < kst; ++ks) {
            int gk = mc*64 + ks*16;
            uint32_t ah[4], al[4];
            uint32_t aoff = (uint32_t)(((w*16 + arow)*72 + ks*16 + acolsel)*2);
            LDSM_X4(ah[0],ah[1],ah[2],ah[3], sb + OU_QH + aoff);
            LDSM_X4(al[0],al[1],al[2],al[3], sb + OU_QL + aoff);
            uint32_t bh4[4][4], bl4[4][4], bh2[2], bl2[2];
            #pragma unroll
            for (int g = 0; g < 4; ++g) {
                uint32_t off = (uint32_t)(((gk + arow)*72 + g*16 + acolsel)*2);
                LDSM_X4T(bh4[g][0],bh4[g][1],bh4[g][2],bh4[g][3], sb + OU_KH + off);
                LDSM_X4T(bl4[g][0],bl4[g][1],bl4[g][2],bl4[g][3], sb + OU_KL + off);
            }
            uint32_t off2 = (uint32_t)(((gk + (lane & 15))*72 + 64)*2);
            LDSM_X2T(bh2[0], bh2[1], sb + OU_KH + off2);
            LDSM_X2T(bl2[0], bl2[1], sb + OU_KL + off2);
            #pragma unroll
            for (int nt = 0; nt < 9; ++nt) {
                uint32_t p0 = (nt < 8) ? bh4[nt>>1][(nt&1)*2]   : bh2[0];
                uint32_t p1 = (nt < 8) ? bh4[nt>>1][(nt&1)*2+1] : bh2[1];
                uint32_t q0 = (nt < 8) ? bl4[nt>>1][(nt&1)*2]   : bl2[0];
                uint32_t q1 = (nt < 8) ? bl4[nt>>1][(nt&1)*2+1] : bl2[1];
                MMA_BF16(acc[nt], ah, p0, p1);
                MMA_BF16(acc[nt], ah, q0, q1);
                MMA_BF16(acc[nt], al, p0, p1);
            }
        }
    }
    float den0 = __shfl_sync(0xffffffffu, acc[8][0], lane & ~3);
    float den1 = __shfl_sync(0xffffffffu, acc[8][2], lane & ~3);
    if (fabsf(den0) <= NSTAB) den0 += 2.f*NSTAB;
    if (fabsf(den1) <= NSTAB) den1 += 2.f*NSTAB;
    float inv0 = 1.f/den0, inv1 = 1.f/den1;
    int r0 = w*16 + (lane >> 2);
    size_t gl0 = (size_t)(b*L_ + l0 + r0), gl1 = gl0 + 8;
    #pragma unroll
    for (int nt = 0; nt < 8; ++nt) {
        int c0 = nt*8 + (lane & 3)*2;
        *(float2*)(g_ctx + gl0*D_ + h*64 + c0) = make_float2(acc[nt][0]*inv0, acc[nt][1]*inv0);
        *(float2*)(g_ctx + gl1*D_ + h*64 + c0) = make_float2(acc[nt][2]*inv1, acc[nt][3]*inv1);
    }
}

// ---------------- launch ----------------
extern "C" void kernel_launch(void* const* d_in, const int* in_sizes, int n_in,
                              void* d_out, int out_size) {
    const float* query = (const float*)d_in[0];
    const float* key   = (const float*)d_in[1];
    const float* value = (const float*)d_in[2];
    const float* mask  = (const float*)d_in[3];
    const float* Wq = (const float*)d_in[4];
    const float* bq = (const float*)d_in[5];
    const float* Wk = (const float*)d_in[6];
    const float* bk = (const float*)d_in[7];
    const float* Wv = (const float*)d_in[8];
    const float* bv = (const float*)d_in[9];
    const float* Wo = (const float*)d_in[10];
    const float* bo = (const float*)d_in[11];
    const float* Wf = (const float*)d_in[12];

    float *Qp, *Kp, *Vp, *ctx, *qpr, *kpr;
    cudaGetSymbolAddress((void**)&Qp,  g_Qp);
    cudaGetSymbolAddress((void**)&Kp,  g_Kp);
    cudaGetSymbolAddress((void**)&Vp,  g_Vp);
    cudaGetSymbolAddress((void**)&ctx, g_ctx);
    cudaGetSymbolAddress((void**)&qpr, g_qprime);
    cudaGetSymbolAddress((void**)&kpr, g_kprime);

    cudaFuncSetAttribute(proj_kernel, cudaFuncAttributeMaxDynamicSharedMemorySize, PJ_SMEM);
    cudaFuncSetAttribute(kv_mma,      cudaFuncAttributeMaxDynamicSharedMemorySize, KV_SMEMB);
    cudaFuncSetAttribute(out_mma,     cudaFuncAttributeMaxDynamicSharedMemorySize, OU_SMEM);

    init_kernel<<<1, 32>>>();

    dim3 gg(D_/128, BL/128);
    gemm_mma<<<gg, 256>>>(query, Wq, bq, Qp);
    gemm_mma<<<gg, 256>>>(key,   Wk, bk, Kp);
    gemm_mma<<<gg, 256>>>(value, Wv, bv, Vp);

    hk_kernel<<<(BH*L_)/256, 256>>>();

    dim3 pg(L_/64, H_, B_);
    proj_kernel<<<pg, 256, PJ_SMEM>>>(Qp, Wf, mask, qpr, 0);
    proj_kernel<<<pg, 256, PJ_SMEM>>>(Kp, Wf, mask, kpr, 1);

    kv_mma<<<dim3(SPLIT, BH), 288, KV_SMEMB>>>();
    kv_reduce<<<(KVSZ2 + 255)/256, 256>>>();

    out_mma<<<dim3(L_/128, H_, B_), 256, OU_SMEM>>>(nullptr);

    gemm_mma<<<gg, 256>>>(ctx, Wo, bo, (float*)d_out);
}

// round 7
// speedup vs baseline: 1.2608x; 1.0366x over previous
#include <cuda_runtime.h>
#include <cstdint>
#include <math.h>

#define B_   2
#define L_   8192
#define D_   1024
#define H_   16
#define DH_  64
#define M_   266
#define MP2  288
#define BL   (B_*L_)
#define BH   (B_*H_)

#define SCALE  0.17677669529663687f
#define SCALE2 0.03125f
#define NC     0.061313932f
#define KEPS   1e-4f
#define NSTAB  1e-6f

#define SPLIT  16
#define KVROW  272
#define KVCOL  72
#define KVSZ2  (BH*KVROW*KVCOL)

// ---------------- device scratch ----------------
__device__ float g_Qp[BL*D_];
__device__ float g_Kp[BL*D_];
__device__ float g_Vp[BL*D_];
__device__ float g_ctx[BL*D_];
__device__ float g_hk[BH*L_];
__device__ unsigned int g_kstab;
__device__ float g_qprime[BH*L_*MP2];
__device__ float g_kprime[BH*L_*MP2];
__device__ float g_kv[KVSZ2];
__device__ float g_kvpart[(size_t)SPLIT*KVSZ2];

// ================= helpers =================
__device__ __forceinline__ uint32_t smem_u32(const void* p) {
    uint32_t a;
    asm("{ .reg .u64 t; cvta.to.shared.u64 t, %1; cvt.u32.u64 %0, t; }" : "=r"(a) : "l"(p));
    return a;
}
__device__ __forceinline__ void cvt_split(float4 v, uint32_t& h01, uint32_t& h23,
                                          uint32_t& l01, uint32_t& l23) {
    asm("cvt.rn.bf16x2.f32 %0, %1, %2;" : "=r"(h01) : "f"(v.y), "f"(v.x));
    asm("cvt.rn.bf16x2.f32 %0, %1, %2;" : "=r"(h23) : "f"(v.w), "f"(v.z));
    float r0 = v.x - __uint_as_float(h01 << 16);
    float r1 = v.y - __uint_as_float(h01 & 0xffff0000u);
    float r2 = v.z - __uint_as_float(h23 << 16);
    float r3 = v.w - __uint_as_float(h23 & 0xffff0000u);
    asm("cvt.rn.bf16x2.f32 %0, %1, %2;" : "=r"(l01) : "f"(r1), "f"(r0));
    asm("cvt.rn.bf16x2.f32 %0, %1, %2;" : "=r"(l23) : "f"(r3), "f"(r2));
}
#define LDSM_X4(r0,r1,r2,r3,addr) \
    asm volatile("ldmatrix.sync.aligned.m8n8.x4.shared.b16 {%0,%1,%2,%3}, [%4];" \
        : "=r"(r0),"=r"(r1),"=r"(r2),"=r"(r3) : "r"(addr))
#define LDSM_X4T(r0,r1,r2,r3,addr) \
    asm volatile("ldmatrix.sync.aligned.m8n8.x4.trans.shared.b16 {%0,%1,%2,%3}, [%4];" \
        : "=r"(r0),"=r"(r1),"=r"(r2),"=r"(r3) : "r"(addr))
#define LDSM_X2T(r0,r1,addr) \
    asm volatile("ldmatrix.sync.aligned.m8n8.x2.trans.shared.b16 {%0,%1}, [%2];" \
        : "=r"(r0),"=r"(r1) : "r"(addr))
#define MMA_BF16(d,a,b0_,b1_) \
    asm volatile("mma.sync.aligned.m16n8k16.row.col.f32.bf16.bf16.f32 " \
        "{%0,%1,%2,%3}, {%4,%5,%6,%7}, {%8,%9}, {%0,%1,%2,%3};" \
        : "+f"((d)[0]),"+f"((d)[1]),"+f"((d)[2]),"+f"((d)[3]) \
        : "r"((a)[0]),"r"((a)[1]),"r"((a)[2]),"r"((a)[3]),"r"(b0_),"r"(b1_))
#define CP16(dst, src) \
    asm volatile("cp.async.cg.shared.global [%0], [%1], 16;" :: "r"(dst), "l"(src))
#define CP_COMMIT() asm volatile("cp.async.commit_group;" ::: "memory")
#define CP_WAIT1()  asm volatile("cp.async.wait_group 1;" ::: "memory")
#define CP_WAIT0()  asm volatile("cp.async.wait_group 0;" ::: "memory")

// ================= bf16x3 GEMM with cp.async double-buffered staging =================
#define AST 40
// dyn smem layout (bytes): stage s fp32: A at s*32768, W at s*32768+16384 (2 stages)
// bf16 tiles: Ah 65536, Al 75776, Wh 86016, Wl 96256; total 106496
#define G_TAH 65536
#define G_TAL 75776
#define G_TWH 86016
#define G_TWL 96256
#define G_SMEM 106496

__global__ __launch_bounds__(256, 2) void gemm_mma(const float* __restrict__ A,
                                                   const float* __restrict__ W,
                                                   const float* __restrict__ bias,
                                                   float* __restrict__ C) {
    extern __shared__ char smg[];
    const uint32_t sb = smem_u32(smg);
    const int tid = threadIdx.x, lane = tid & 31, wid = tid >> 5;
    const int wm = wid & 1, wn = wid >> 1;
    const size_t mbase = (size_t)blockIdx.y * 128, nbase = (size_t)blockIdx.x * 128;
    const float* Ab = A + mbase * D_;
    const float* Wb = W + nbase * D_;

    const uint32_t aH = sb + G_TAH, aL = sb + G_TAL;
    const uint32_t bH = sb + G_TWH, bL = sb + G_TWL;

    const int arow = lane & 15, acolsel = (lane >> 4) << 3;
    const int brow = (lane & 7) + ((lane >> 4) << 3), bcolsel = ((lane >> 3) & 1) << 3;

    float acc[4][4][4];
    #pragma unroll
    for (int i = 0; i < 4; ++i)
        #pragma unroll
        for (int j = 0; j < 4; ++j)
            #pragma unroll
            for (int k = 0; k < 4; ++k) acc[i][j][k] = 0.f;

    // prefetch chunk 0 into stage 0
    {
        uint32_t stA = sb, stW = sb + 16384;
        #pragma unroll
        for (int j = 0; j < 4; ++j) {
            int fidx = tid + j * 256, rr = fidx >> 3, uu = fidx & 7;
            CP16(stA + (rr*32 + uu*4)*4, Ab + (size_t)rr*D_ + uu*4);
            CP16(stW + (rr*32 + uu*4)*4, Wb + (size_t)rr*D_ + uu*4);
        }
        CP_COMMIT();
    }

    for (int kc = 0; kc < 32; ++kc) {
        int s = kc & 1;
        if (kc + 1 < 32) {
            uint32_t stA = sb + (s^1)*32768, stW = stA + 16384;
            #pragma unroll
            for (int j = 0; j < 4; ++j) {
                int fidx = tid + j * 256, rr = fidx >> 3, uu = fidx & 7;
                CP16(stA + (rr*32 + uu*4)*4, Ab + (size_t)rr*D_ + (kc+1)*32 + uu*4);
                CP16(stW + (rr*32 + uu*4)*4, Wb + (size_t)rr*D_ + (kc+1)*32 + uu*4);
            }
            CP_COMMIT();
            CP_WAIT1();
        } else {
            CP_WAIT0();
        }
        __syncthreads();
        // convert staged fp32 -> bf16 hi/lo tiles
        {
            const float* stA = (const float*)(smg + s*32768);
            const float* stW = (const float*)(smg + s*32768 + 16384);
            #pragma unroll
            for (int j = 0; j < 4; ++j) {
                int fidx = tid + j * 256, rr = fidx >> 3, uu = fidx & 7;
                float4 v = *(const float4*)(stA + rr*32 + uu*4);
                uint32_t h01, h23, l01, l23;
                cvt_split(v, h01, h23, l01, l23);
                *(uint2*)(smg + G_TAH + (rr*AST + uu*4)*2) = make_uint2(h01, h23);
                *(uint2*)(smg + G_TAL + (rr*AST + uu*4)*2) = make_uint2(l01, l23);
                float4 w = *(const float4*)(stW + rr*32 + uu*4);
                cvt_split(w, h01, h23, l01, l23);
                *(uint2*)(smg + G_TWH + (rr*AST + uu*4)*2) = make_uint2(h01, h23);
                *(uint2*)(smg + G_TWL + (rr*AST + uu*4)*2) = make_uint2(l01, l23);
            }
        }
        __syncthreads();

        #pragma unroll
        for (int ks = 0; ks < 2; ++ks) {
            uint32_t af[4][4], bhF[2][4], blF[2][4];
            #pragma unroll
            for (int mt = 0; mt < 4; ++mt) {
                uint32_t off = (uint32_t)(((wm*64 + mt*16 + arow)*AST + ks*16 + acolsel)*2);
                LDSM_X4(af[mt][0], af[mt][1], af[mt][2], af[mt][3], aH + off);
            }
            #pragma unroll
            for (int bp = 0; bp < 2; ++bp) {
                uint32_t off = (uint32_t)(((wn*32 + bp*16 + brow)*AST + ks*16 + bcolsel)*2);
                LDSM_X4(bhF[bp][0], bhF[bp][1], bhF[bp][2], bhF[bp][3], bH + off);
                LDSM_X4(blF[bp][0], blF[bp][1], blF[bp][2], blF[bp][3], bL + off);
            }
            #pragma unroll
            for (int mt = 0; mt < 4; ++mt)
                #pragma unroll
                for (int nt = 0; nt < 4; ++nt) {
                    MMA_BF16(acc[mt][nt], af[mt], bhF[nt>>1][(nt&1)*2], bhF[nt>>1][(nt&1)*2+1]);
                    MMA_BF16(acc[mt][nt], af[mt], blF[nt>>1][(nt&1)*2], blF[nt>>1][(nt&1)*2+1]);
                }
            #pragma unroll
            for (int mt = 0; mt < 4; ++mt) {
                uint32_t off = (uint32_t)(((wm*64 + mt*16 + arow)*AST + ks*16 + acolsel)*2);
                LDSM_X4(af[mt][0], af[mt][1], af[mt][2], af[mt][3], aL + off);
            }
            #pragma unroll
            for (int mt = 0; mt < 4; ++mt)
                #pragma unroll
                for (int nt = 0; nt < 4; ++nt)
                    MMA_BF16(acc[mt][nt], af[mt], bhF[nt>>1][(nt&1)*2], bhF[nt>>1][(nt&1)*2+1]);
        }
    }
    #pragma unroll
    for (int mt = 0; mt < 4; ++mt) {
        size_t r0 = mbase + wm*64 + mt*16 + (lane >> 2);
        #pragma unroll
        for (int nt = 0; nt < 4; ++nt) {
            int col = (int)nbase + wn*32 + nt*8 + 2*(lane & 3);
            float bx = bias[col], by = bias[col+1];
            *(float2*)(C + r0*D_ + col)     = make_float2(acc[mt][nt][0]+bx, acc[mt][nt][1]+by);
            *(float2*)(C + (r0+8)*D_ + col) = make_float2(acc[mt][nt][2]+bx, acc[mt][nt][3]+by);
        }
    }
}

// ---------------- init / hk ----------------
__global__ void init_kernel() { if (threadIdx.x == 0) g_kstab = 0xFF800000u; }

__global__ __launch_bounds__(256) void hk_kernel() {
    int gid = blockIdx.x * 256 + threadIdx.x;
    int b = gid / (H_*L_), rem = gid % (H_*L_), h = rem / L_, l = rem % L_;
    const float4* row = (const float4*)(g_Kp + (size_t)(b*L_ + l)*D_ + h*DH_);
    float s = 0.f;
    #pragma unroll
    for (int t = 0; t < 16; ++t) {
        float4 v = row[t];
        s = fmaf(v.x,v.x,s); s = fmaf(v.y,v.y,s); s = fmaf(v.z,v.z,s); s = fmaf(v.w,v.w,s);
    }
    float hk = -0.5f * SCALE2 * s;
    g_hk[gid] = hk;
    float m = hk;
    #pragma unroll
    for (int o = 16; o > 0; o >>= 1) m = fmaxf(m, __shfl_xor_sync(0xffffffffu, m, o));
    __shared__ float wmax[8];
    if ((threadIdx.x & 31) == 0) wmax[threadIdx.x >> 5] = m;
    __syncthreads();
    if (threadIdx.x == 0) {
        float bm = wmax[0];
        #pragma unroll
        for (int w = 1; w < 8; ++w) bm = fmaxf(bm, wmax[w]);
        atomicMin(&g_kstab, __float_as_uint(bm));
    }
}

// ================= proj kernel =================
#define PJ_WH 0
#define PJ_WL 41472
#define PJ_XH 82944
#define PJ_XL 92160
#define PJ_SMEM 101376
__global__ __launch_bounds__(256, 1) void proj_kernel(const float* __restrict__ X,
                                                      const float* __restrict__ Wf,
                                                      const float* __restrict__ mask,
                                                      float* __restrict__ Out, int isK) {
    extern __shared__ char sm[];
    const uint32_t sb = smem_u32(sm);
    const int tid = threadIdx.x, lane = tid & 31, w = tid >> 5;
    const int h = blockIdx.y, b = blockIdx.z, bh = b*H_ + h;
    const int l0 = blockIdx.x * 64;

    for (int i = tid; i < (PJ_XH) / 4; i += 256) ((uint32_t*)sm)[i] = 0;
    __syncthreads();
    for (int i = tid; i < 266*16; i += 256) {
        int r = i >> 4, u = i & 15;
        float4 v = *(const float4*)(Wf + r*64 + u*4);
        uint32_t h01,h23,l01,l23; cvt_split(v,h01,h23,l01,l23);
        *(uint2*)(sm + PJ_WH + (r*72 + u*4)*2) = make_uint2(h01,h23);
        *(uint2*)(sm + PJ_WL + (r*72 + u*4)*2) = make_uint2(l01,l23);
    }
    for (int i = tid; i < 64*16; i += 256) {
        int r = i >> 4, u = i & 15;
        float4 v = *(const float4*)(X + (size_t)(b*L_ + l0 + r)*D_ + h*64 + u*4);
        v.x*=SCALE; v.y*=SCALE; v.z*=SCALE; v.w*=SCALE;
        uint32_t h01,h23,l01,l23; cvt_split(v,h01,h23,l01,l23);
        *(uint2*)(sm + PJ_XH + (r*72 + u*4)*2) = make_uint2(h01,h23);
        *(uint2*)(sm + PJ_XL + (r*72 + u*4)*2) = make_uint2(l01,l23);
    }
    __syncthreads();

    const int wl = w >> 1, wn = w & 1;
    const int arow = lane & 15, acolsel = (lane >> 4) << 3;
    const int brow = (lane & 7) + ((lane >> 4) << 3), bcolsel = ((lane >> 3) & 1) << 3;

    float acc[18][4];
    #pragma unroll
    for (int i = 0; i < 18; ++i)
        #pragma unroll
        for (int k = 0; k < 4; ++k) acc[i][k] = 0.f;

    #pragma unroll
    for (int ks = 0; ks < 4; ++ks) {
        uint32_t ah[4], al[4];
        uint32_t aoff = (uint32_t)(((wl*16 + arow)*72 + ks*16 + acolsel)*2);
        LDSM_X4(ah[0],ah[1],ah[2],ah[3], sb + PJ_XH + aoff);
        LDSM_X4(al[0],al[1],al[2],al[3], sb + PJ_XL + aoff);
        uint32_t bh9[9][4], bl9[9][4];
        #pragma unroll
        for (int j = 0; j < 9; ++j) {
            int g = wn + 2*j;
            uint32_t off = (uint32_t)(((g*16 + brow)*72 + ks*16 + bcolsel)*2);
            LDSM_X4(bh9[j][0],bh9[j][1],bh9[j][2],bh9[j][3], sb + PJ_WH + off);
            LDSM_X4(bl9[j][0],bl9[j][1],bl9[j][2],bl9[j][3], sb + PJ_WL + off);
        }
        #pragma unroll
        for (int j = 0; j < 9; ++j)
            #pragma unroll
            for (int half = 0; half < 2; ++half) {
                int nt = 2*j + half;
                MMA_BF16(acc[nt], ah, bh9[j][half*2], bh9[j][half*2+1]);
                MMA_BF16(acc[nt], ah, bl9[j][half*2], bl9[j][half*2+1]);
                MMA_BF16(acc[nt], al, bh9[j][half*2], bh9[j][half*2+1]);
            }
    }

    int r0 = wl*16 + (lane >> 2);
    int gl0 = l0 + r0, gl1 = gl0 + 8;
    float add0 = 0.f, add1 = 0.f, mk0 = 1.f, mk1 = 1.f;
    if (isK) {
        float kst = __uint_as_float(g_kstab);
        add0 = g_hk[(size_t)bh*L_ + gl0] - kst;
        add1 = g_hk[(size_t)bh*L_ + gl1] - kst;
        mk0 = mask[b*L_ + gl0];
        mk1 = mask[b*L_ + gl1];
    }
    float* O0 = Out + ((size_t)bh*L_ + gl0)*MP2;
    float* O1 = Out + ((size_t)bh*L_ + gl1)*MP2;
    #pragma unroll
    for (int j = 0; j < 9; ++j)
        #pragma unroll
        for (int half = 0; half < 2; ++half) {
            int nt = 2*j + half;
            int c0 = (wn + 2*j)*16 + half*8 + (lane & 3)*2;
            float2 v0, v1;
            v0.x = (c0   < M_) ? NC*(__expf(acc[nt][0]+add0)+KEPS)*mk0 : 0.f;
            v0.y = (c0+1 < M_) ? NC*(__expf(acc[nt][1]+add0)+KEPS)*mk0 : 0.f;
            v1.x = (c0   < M_) ? NC*(__expf(acc[nt][2]+add1)+KEPS)*mk1 : 0.f;
            v1.y = (c0+1 < M_) ? NC*(__expf(acc[nt][3]+add1)+KEPS)*mk1 : 0.f;
            *(float2*)(O0 + c0) = v0;
            *(float2*)(O1 + c0) = v1;
        }
}

// ================= kv kernel =================
#define KST 296
#define KV_KH 0
#define KV_KL 37888
#define KV_VH 75776
#define KV_VL 84992
#define KV_SMEMB 94208
__global__ __launch_bounds__(288, 1) void kv_mma() {
    extern __shared__ char sm[];
    const uint32_t sb = smem_u32(sm);
    const int tid = threadIdx.x, lane = tid & 31, w = tid >> 5;
    const int split = blockIdx.x, bh = blockIdx.y;
    const int b = bh / H_, h = bh % H_;
    const int arow = lane & 15, acolsel = (lane >> 4) << 3;
    const int brow = (lane & 7) + ((lane >> 4) << 3), bcolsel = ((lane >> 3) & 1) << 3;

    float acc[2][9][4];
    #pragma unroll
    for (int t = 0; t < 2; ++t)
        #pragma unroll
        for (int n = 0; n < 9; ++n)
            #pragma unroll
            for (int k = 0; k < 4; ++k) acc[t][n][k] = 0.f;

    for (int c = 0; c < 8; ++c) {
        int lb = split*512 + c*64;
        __syncthreads();
        for (int i = tid; i < 64*72; i += 288) {
            int r = i / 72, u = i % 72;
            float4 v = *(const float4*)(g_kprime + ((size_t)bh*L_ + lb + r)*MP2 + u*4);
            uint32_t h01,h23,l01,l23; cvt_split(v,h01,h23,l01,l23);
            *(uint2*)(sm + KV_KH + (r*KST + u*4)*2) = make_uint2(h01,h23);
            *(uint2*)(sm + KV_KL + (r*KST + u*4)*2) = make_uint2(l01,l23);
        }
        for (int i = tid; i < 64*18; i += 288) {
            int r = i / 18, u = i % 18;
            float4 v;
            if (u < 16) v = *(const float4*)(g_Vp + (size_t)(b*L_ + lb + r)*D_ + h*64 + u*4);
            else if (u == 16) v = make_float4(1.f, 0.f, 0.f, 0.f);
            else v = make_float4(0.f, 0.f, 0.f, 0.f);
            uint32_t h01,h23,l01,l23; cvt_split(v,h01,h23,l01,l23);
            *(uint2*)(sm + KV_VH + (r*72 + u*4)*2) = make_uint2(h01,h23);
            *(uint2*)(sm + KV_VL + (r*72 + u*4)*2) = make_uint2(l01,l23);
        }
        __syncthreads();
        #pragma unroll
        for (int ks = 0; ks < 4; ++ks) {
            uint32_t ah2[2][4], al2[2][4];
            #pragma unroll
            for (int t = 0; t < 2; ++t) {
                uint32_t off = (uint32_t)(((ks*16 + brow)*KST + (2*w + t)*16 + bcolsel)*2);
                LDSM_X4T(ah2[t][0],ah2[t][1],ah2[t][2],ah2[t][3], sb + KV_KH + off);
                LDSM_X4T(al2[t][0],al2[t][1],al2[t][2],al2[t][3], sb + KV_KL + off);
            }
            uint32_t bh4[4][4], bl4[4][4], bh2[2], bl2[2];
            #pragma unroll
            for (int g = 0; g < 4; ++g) {
                uint32_t off = (uint32_t)(((ks*16 + arow)*72 + g*16 + acolsel)*2);
                LDSM_X4T(bh4[g][0],bh4[g][1],bh4[g][2],bh4[g][3], sb + KV_VH + off);
                LDSM_X4T(bl4[g][0],bl4[g][1],bl4[g][2],bl4[g][3], sb + KV_VL + off);
            }
            uint32_t off2 = (uint32_t)(((ks*16 + (lane & 15))*72 + 64)*2);
            LDSM_X2T(bh2[0], bh2[1], sb + KV_VH + off2);
            LDSM_X2T(bl2[0], bl2[1], sb + KV_VL + off2);
            #pragma unroll
            for (int t = 0; t < 2; ++t)
                #pragma unroll
                for (int nt = 0; nt < 9; ++nt) {
                    uint32_t p0 = (nt < 8) ? bh4[nt>>1][(nt&1)*2]   : bh2[0];
                    uint32_t p1 = (nt < 8) ? bh4[nt>>1][(nt&1)*2+1] : bh2[1];
                    uint32_t q0 = (nt < 8) ? bl4[nt>>1][(nt&1)*2]   : bl2[0];
                    uint32_t q1 = (nt < 8) ? bl4[nt>>1][(nt&1)*2+1] : bl2[1];
                    MMA_BF16(acc[t][nt], ah2[t], p0, p1);
                    MMA_BF16(acc[t][nt], ah2[t], q0, q1);
                    MMA_BF16(acc[t][nt], al2[t], p0, p1);
                }
        }
    }
    float* base = g_kvpart + (size_t)(split*BH + bh)*KVROW*KVCOL;
    #pragma unroll
    for (int t = 0; t < 2; ++t) {
        int m0 = w*32 + t*16;
        if (m0 < KVROW) {
            int r0 = m0 + (lane >> 2);
            #pragma unroll
            for (int nt = 0; nt < 9; ++nt) {
                int c0 = nt*8 + (lane & 3)*2;
                *(float2*)(base + (size_t)r0*KVCOL + c0)     = make_float2(acc[t][nt][0], acc[t][nt][1]);
                *(float2*)(base + (size_t)(r0+8)*KVCOL + c0) = make_float2(acc[t][nt][2], acc[t][nt][3]);
            }
        }
    }
}

__global__ void kv_reduce() {
    int idx = blockIdx.x * 256 + threadIdx.x;
    if (idx < KVSZ2) {
        float s = 0.f;
        #pragma unroll
        for (int p = 0; p < SPLIT; ++p) s += g_kvpart[(size_t)p*KVSZ2 + idx];
        g_kv[idx] = s;
    }
}

// ================= out kernel =================
#define OU_QH 0
#define OU_QL 18432
#define OU_KH 36864
#define OU_KL 78336
#define OU_SMEM 119808
__global__ __launch_bounds__(256, 1) void out_mma(const float* __restrict__ dummy) {
    extern __shared__ char sm[];
    const uint32_t sb = smem_u32(sm);
    const int tid = threadIdx.x, lane = tid & 31, w = tid >> 5;
    const int h = blockIdx.y, b = blockIdx.z, bh = b*H_ + h;
    const int l0 = blockIdx.x * 128;
    const int arow = lane & 15, acolsel = (lane >> 4) << 3;

    for (int i = tid; i < (OU_SMEM - OU_KH) / 4; i += 256) ((uint32_t*)(sm + OU_KH))[i] = 0;
    __syncthreads();
    for (int i = tid; i < KVROW*18; i += 256) {
        int r = i / 18, u = i % 18;
        float4 v = *(const float4*)(g_kv + ((size_t)bh*KVROW + r)*KVCOL + u*4);
        uint32_t h01,h23,l01,l23; cvt_split(v,h01,h23,l01,l23);
        *(uint2*)(sm + OU_KH + (r*72 + u*4)*2) = make_uint2(h01,h23);
        *(uint2*)(sm + OU_KL + (r*72 + u*4)*2) = make_uint2(l01,l23);
    }

    float acc[9][4];
    #pragma unroll
    for (int n = 0; n < 9; ++n)
        #pragma unroll
        for (int k = 0; k < 4; ++k) acc[n][k] = 0.f;

    for (int mc = 0; mc < 5; ++mc) {
        int kst = (mc < 4) ? 4 : 2;
        int nf4 = kst * 4;
        __syncthreads();
        for (int i = tid; i < 128*nf4; i += 256) {
            int r = i / nf4, u = i % nf4;
            float4 v = *(const float4*)(g_qprime + ((size_t)bh*L_ + l0 + r)*MP2 + mc*64 + u*4);
            uint32_t h01,h23,l01,l23; cvt_split(v,h01,h23,l01,l23);
            *(uint2*)(sm + OU_QH + (r*72 + u*4)*2) = make_uint2(h01,h23);
            *(uint2*)(sm + OU_QL + (r*72 + u*4)*2) = make_uint2(l01,l23);
        }
        __syncthreads();
        for (int ks = 0; ks < kst; ++ks) {
            int gk = mc*64 + ks*16;
            uint32_t ah[4], al[4];
            uint32_t aoff = (uint32_t)(((w*16 + arow)*72 + ks*16 + acolsel)*2);
            LDSM_X4(ah[0],ah[1],ah[2],ah[3], sb + OU_QH + aoff);
            LDSM_X4(al[0],al[1],al[2],al[3], sb + OU_QL + aoff);
            uint32_t bh4[4][4], bl4[4][4], bh2[2], bl2[2];
            #pragma unroll
            for (int g = 0; g < 4; ++g) {
                uint32_t off = (uint32_t)(((gk + arow)*72 + g*16 + acolsel)*2);
                LDSM_X4T(bh4[g][0],bh4[g][1],bh4[g][2],bh4[g][3], sb + OU_KH + off);
                LDSM_X4T(bl4[g][0],bl4[g][1],bl4[g][2],bl4[g][3], sb + OU_KL + off);
            }
            uint32_t off2 = (uint32_t)(((gk + (lane & 15))*72 + 64)*2);
            LDSM_X2T(bh2[0], bh2[1], sb + OU_KH + off2);
            LDSM_X2T(bl2[0], bl2[1], sb + OU_KL + off2);
            #pragma unroll
            for (int nt = 0; nt < 9; ++nt) {
                uint32_t p0 = (nt < 8) ? bh4[nt>>1][(nt&1)*2]   : bh2[0];
                uint32_t p1 = (nt < 8) ? bh4[nt>>1][(nt&1)*2+1] : bh2[1];
                uint32_t q0 = (nt < 8) ? bl4[nt>>1][(nt&1)*2]   : bl2[0];
                uint32_t q1 = (nt < 8) ? bl4[nt>>1][(nt&1)*2+1] : bl2[1];
                MMA_BF16(acc[nt], ah, p0, p1);
                MMA_BF16(acc[nt], ah, q0, q1);
                MMA_BF16(acc[nt], al, p0, p1);
            }
        }
    }
    float den0 = __shfl_sync(0xffffffffu, acc[8][0], lane & ~3);
    float den1 = __shfl_sync(0xffffffffu, acc[8][2], lane & ~3);
    if (fabsf(den0) <= NSTAB) den0 += 2.f*NSTAB;
    if (fabsf(den1) <= NSTAB) den1 += 2.f*NSTAB;
    float inv0 = 1.f/den0, inv1 = 1.f/den1;
    int r0 = w*16 + (lane >> 2);
    size_t gl0 = (size_t)(b*L_ + l0 + r0), gl1 = gl0 + 8;
    #pragma unroll
    for (int nt = 0; nt < 8; ++nt) {
        int c0 = nt*8 + (lane & 3)*2;
        *(float2*)(g_ctx + gl0*D_ + h*64 + c0) = make_float2(acc[nt][0]*inv0, acc[nt][1]*inv0);
        *(float2*)(g_ctx + gl1*D_ + h*64 + c0) = make_float2(acc[nt][2]*inv1, acc[nt][3]*inv1);
    }
}

// ---------------- launch ----------------
extern "C" void kernel_launch(void* const* d_in, const int* in_sizes, int n_in,
                              void* d_out, int out_size) {
    const float* query = (const float*)d_in[0];
    const float* key   = (const float*)d_in[1];
    const float* value = (const float*)d_in[2];
    const float* mask  = (const float*)d_in[3];
    const float* Wq = (const float*)d_in[4];
    const float* bq = (const float*)d_in[5];
    const float* Wk = (const float*)d_in[6];
    const float* bk = (const float*)d_in[7];
    const float* Wv = (const float*)d_in[8];
    const float* bv = (const float*)d_in[9];
    const float* Wo = (const float*)d_in[10];
    const float* bo = (const float*)d_in[11];
    const float* Wf = (const float*)d_in[12];

    float *Qp, *Kp, *Vp, *ctx, *qpr, *kpr;
    cudaGetSymbolAddress((void**)&Qp,  g_Qp);
    cudaGetSymbolAddress((void**)&Kp,  g_Kp);
    cudaGetSymbolAddress((void**)&Vp,  g_Vp);
    cudaGetSymbolAddress((void**)&ctx, g_ctx);
    cudaGetSymbolAddress((void**)&qpr, g_qprime);
    cudaGetSymbolAddress((void**)&kpr, g_kprime);

    cudaFuncSetAttribute(gemm_mma,    cudaFuncAttributeMaxDynamicSharedMemorySize, G_SMEM);
    cudaFuncSetAttribute(proj_kernel, cudaFuncAttributeMaxDynamicSharedMemorySize, PJ_SMEM);
    cudaFuncSetAttribute(kv_mma,      cudaFuncAttributeMaxDynamicSharedMemorySize, KV_SMEMB);
    cudaFuncSetAttribute(out_mma,     cudaFuncAttributeMaxDynamicSharedMemorySize, OU_SMEM);

    init_kernel<<<1, 32>>>();

    dim3 gg(D_/128, BL/128);
    gemm_mma<<<gg, 256, G_SMEM>>>(query, Wq, bq, Qp);
    gemm_mma<<<gg, 256, G_SMEM>>>(key,   Wk, bk, Kp);
    gemm_mma<<<gg, 256, G_SMEM>>>(value, Wv, bv, Vp);

    hk_kernel<<<(BH*L_)/256, 256>>>();

    dim3 pg(L_/64, H_, B_);
    proj_kernel<<<pg, 256, PJ_SMEM>>>(Qp, Wf, mask, qpr, 0);
    proj_kernel<<<pg, 256, PJ_SMEM>>>(Kp, Wf, mask, kpr, 1);

    kv_mma<<<dim3(SPLIT, BH), 288, KV_SMEMB>>>();
    kv_reduce<<<(KVSZ2 + 255)/256, 256>>>();

    out_mma<<<dim3(L_/128, H_, B_), 256, OU_SMEM>>>(nullptr);

    gemm_mma<<<gg, 256, G_SMEM>>>(ctx, Wo, bo, (float*)d_out);
}

// round 8
// speedup vs baseline: 1.4584x; 1.1567x over previous
#include <cuda_runtime.h>
#include <cstdint>
#include <math.h>

#define B_   2
#define L_   8192
#define D_   1024
#define H_   16
#define DH_  64
#define M_   266
#define BL   (B_*L_)
#define BH   (B_*H_)

#define SCALE  0.17677669529663687f
#define SCALE2 0.03125f
#define NC     0.061313932f
#define KEPS   1e-4f
#define NSTAB  1e-6f

#define SPLIT  16
#define KVROW  272
#define KVCOL  72
#define KVSZ2  (BH*KVROW*KVCOL)

// ---------------- device scratch ----------------
__device__ float g_Qp[BL*D_];
__device__ float g_Kp[BL*D_];
__device__ float g_Vp[BL*D_];
__device__ float g_ctx[BL*D_];
__device__ float g_hk[BH*L_];
__device__ unsigned int g_kstab;
__device__ float g_kv[KVSZ2];
__device__ float g_kvpart[(size_t)SPLIT*KVSZ2];

// ================= helpers =================
__device__ __forceinline__ uint32_t smem_u32(const void* p) {
    uint32_t a;
    asm("{ .reg .u64 t; cvta.to.shared.u64 t, %1; cvt.u32.u64 %0, t; }" : "=r"(a) : "l"(p));
    return a;
}
__device__ __forceinline__ void cvt_split(float4 v, uint32_t& h01, uint32_t& h23,
                                          uint32_t& l01, uint32_t& l23) {
    asm("cvt.rn.bf16x2.f32 %0, %1, %2;" : "=r"(h01) : "f"(v.y), "f"(v.x));
    asm("cvt.rn.bf16x2.f32 %0, %1, %2;" : "=r"(h23) : "f"(v.w), "f"(v.z));
    float r0 = v.x - __uint_as_float(h01 << 16);
    float r1 = v.y - __uint_as_float(h01 & 0xffff0000u);
    float r2 = v.z - __uint_as_float(h23 << 16);
    float r3 = v.w - __uint_as_float(h23 & 0xffff0000u);
    asm("cvt.rn.bf16x2.f32 %0, %1, %2;" : "=r"(l01) : "f"(r1), "f"(r0));
    asm("cvt.rn.bf16x2.f32 %0, %1, %2;" : "=r"(l23) : "f"(r3), "f"(r2));
}
__device__ __forceinline__ void cvt_split2(float a, float b, uint32_t& hh, uint32_t& ll) {
    asm("cvt.rn.bf16x2.f32 %0, %1, %2;" : "=r"(hh) : "f"(b), "f"(a));
    float ra = a - __uint_as_float(hh << 16);
    float rb = b - __uint_as_float(hh & 0xffff0000u);
    asm("cvt.rn.bf16x2.f32 %0, %1, %2;" : "=r"(ll) : "f"(rb), "f"(ra));
}
#define LDSM_X4(r0,r1,r2,r3,addr) \
    asm volatile("ldmatrix.sync.aligned.m8n8.x4.shared.b16 {%0,%1,%2,%3}, [%4];" \
        : "=r"(r0),"=r"(r1),"=r"(r2),"=r"(r3) : "r"(addr))
#define LDSM_X4T(r0,r1,r2,r3,addr) \
    asm volatile("ldmatrix.sync.aligned.m8n8.x4.trans.shared.b16 {%0,%1,%2,%3}, [%4];" \
        : "=r"(r0),"=r"(r1),"=r"(r2),"=r"(r3) : "r"(addr))
#define LDSM_X2T(r0,r1,addr) \
    asm volatile("ldmatrix.sync.aligned.m8n8.x2.trans.shared.b16 {%0,%1}, [%2];" \
        : "=r"(r0),"=r"(r1) : "r"(addr))
#define MMA_BF16(d,a,b0_,b1_) \
    asm volatile("mma.sync.aligned.m16n8k16.row.col.f32.bf16.bf16.f32 " \
        "{%0,%1,%2,%3}, {%4,%5,%6,%7}, {%8,%9}, {%0,%1,%2,%3};" \
        : "+f"((d)[0]),"+f"((d)[1]),"+f"((d)[2]),"+f"((d)[3]) \
        : "r"((a)[0]),"r"((a)[1]),"r"((a)[2]),"r"((a)[3]),"r"(b0_),"r"(b1_))
#define CP16(dst, src) \
    asm volatile("cp.async.cg.shared.global [%0], [%1], 16;" :: "r"(dst), "l"(src))
#define CP_COMMIT() asm volatile("cp.async.commit_group;" ::: "memory")
#define CP_WAIT1()  asm volatile("cp.async.wait_group 1;" ::: "memory")
#define CP_WAIT0()  asm volatile("cp.async.wait_group 0;" ::: "memory")

// ================= bf16x3 GEMM with cp.async (unchanged from R7) =================
#define AST 40
#define G_TAH 65536
#define G_TAL 75776
#define G_TWH 86016
#define G_TWL 96256
#define G_SMEM 106496

__global__ __launch_bounds__(256, 2) void gemm_mma(const float* __restrict__ A,
                                                   const float* __restrict__ W,
                                                   const float* __restrict__ bias,
                                                   float* __restrict__ C) {
    extern __shared__ char smg[];
    const uint32_t sb = smem_u32(smg);
    const int tid = threadIdx.x, lane = tid & 31, wid = tid >> 5;
    const int wm = wid & 1, wn = wid >> 1;
    const size_t mbase = (size_t)blockIdx.y * 128, nbase = (size_t)blockIdx.x * 128;
    const float* Ab = A + mbase * D_;
    const float* Wb = W + nbase * D_;
    const uint32_t aH = sb + G_TAH, aL = sb + G_TAL;
    const uint32_t bH = sb + G_TWH, bL = sb + G_TWL;
    const int arow = lane & 15, acolsel = (lane >> 4) << 3;
    const int brow = (lane & 7) + ((lane >> 4) << 3), bcolsel = ((lane >> 3) & 1) << 3;

    float acc[4][4][4];
    #pragma unroll
    for (int i = 0; i < 4; ++i)
        #pragma unroll
        for (int j = 0; j < 4; ++j)
            #pragma unroll
            for (int k = 0; k < 4; ++k) acc[i][j][k] = 0.f;

    {
        uint32_t stA = sb, stW = sb + 16384;
        #pragma unroll
        for (int j = 0; j < 4; ++j) {
            int fidx = tid + j * 256, rr = fidx >> 3, uu = fidx & 7;
            CP16(stA + (rr*32 + uu*4)*4, Ab + (size_t)rr*D_ + uu*4);
            CP16(stW + (rr*32 + uu*4)*4, Wb + (size_t)rr*D_ + uu*4);
        }
        CP_COMMIT();
    }

    for (int kc = 0; kc < 32; ++kc) {
        int s = kc & 1;
        if (kc + 1 < 32) {
            uint32_t stA = sb + (s^1)*32768, stW = stA + 16384;
            #pragma unroll
            for (int j = 0; j < 4; ++j) {
                int fidx = tid + j * 256, rr = fidx >> 3, uu = fidx & 7;
                CP16(stA + (rr*32 + uu*4)*4, Ab + (size_t)rr*D_ + (kc+1)*32 + uu*4);
                CP16(stW + (rr*32 + uu*4)*4, Wb + (size_t)rr*D_ + (kc+1)*32 + uu*4);
            }
            CP_COMMIT();
            CP_WAIT1();
        } else {
            CP_WAIT0();
        }
        __syncthreads();
        {
            const float* stA = (const float*)(smg + s*32768);
            const float* stW = (const float*)(smg + s*32768 + 16384);
            #pragma unroll
            for (int j = 0; j < 4; ++j) {
                int fidx = tid + j * 256, rr = fidx >> 3, uu = fidx & 7;
                float4 v = *(const float4*)(stA + rr*32 + uu*4);
                uint32_t h01, h23, l01, l23;
                cvt_split(v, h01, h23, l01, l23);
                *(uint2*)(smg + G_TAH + (rr*AST + uu*4)*2) = make_uint2(h01, h23);
                *(uint2*)(smg + G_TAL + (rr*AST + uu*4)*2) = make_uint2(l01, l23);
                float4 w = *(const float4*)(stW + rr*32 + uu*4);
                cvt_split(w, h01, h23, l01, l23);
                *(uint2*)(smg + G_TWH + (rr*AST + uu*4)*2) = make_uint2(h01, h23);
                *(uint2*)(smg + G_TWL + (rr*AST + uu*4)*2) = make_uint2(l01, l23);
            }
        }
        __syncthreads();

        #pragma unroll
        for (int ks = 0; ks < 2; ++ks) {
            uint32_t af[4][4], bhF[2][4], blF[2][4];
            #pragma unroll
            for (int mt = 0; mt < 4; ++mt) {
                uint32_t off = (uint32_t)(((wm*64 + mt*16 + arow)*AST + ks*16 + acolsel)*2);
                LDSM_X4(af[mt][0], af[mt][1], af[mt][2], af[mt][3], aH + off);
            }
            #pragma unroll
            for (int bp = 0; bp < 2; ++bp) {
                uint32_t off = (uint32_t)(((wn*32 + bp*16 + brow)*AST + ks*16 + bcolsel)*2);
                LDSM_X4(bhF[bp][0], bhF[bp][1], bhF[bp][2], bhF[bp][3], bH + off);
                LDSM_X4(blF[bp][0], blF[bp][1], blF[bp][2], blF[bp][3], bL + off);
            }
            #pragma unroll
            for (int mt = 0; mt < 4; ++mt)
                #pragma unroll
                for (int nt = 0; nt < 4; ++nt) {
                    MMA_BF16(acc[mt][nt], af[mt], bhF[nt>>1][(nt&1)*2], bhF[nt>>1][(nt&1)*2+1]);
                    MMA_BF16(acc[mt][nt], af[mt], blF[nt>>1][(nt&1)*2], blF[nt>>1][(nt&1)*2+1]);
                }
            #pragma unroll
            for (int mt = 0; mt < 4; ++mt) {
                uint32_t off = (uint32_t)(((wm*64 + mt*16 + arow)*AST + ks*16 + acolsel)*2);
                LDSM_X4(af[mt][0], af[mt][1], af[mt][2], af[mt][3], aL + off);
            }
            #pragma unroll
            for (int mt = 0; mt < 4; ++mt)
                #pragma unroll
                for (int nt = 0; nt < 4; ++nt)
                    MMA_BF16(acc[mt][nt], af[mt], bhF[nt>>1][(nt&1)*2], bhF[nt>>1][(nt&1)*2+1]);
        }
    }
    #pragma unroll
    for (int mt = 0; mt < 4; ++mt) {
        size_t r0 = mbase + wm*64 + mt*16 + (lane >> 2);
        #pragma unroll
        for (int nt = 0; nt < 4; ++nt) {
            int col = (int)nbase + wn*32 + nt*8 + 2*(lane & 3);
            float bx = bias[col], by = bias[col+1];
            *(float2*)(C + r0*D_ + col)     = make_float2(acc[mt][nt][0]+bx, acc[mt][nt][1]+by);
            *(float2*)(C + (r0+8)*D_ + col) = make_float2(acc[mt][nt][2]+bx, acc[mt][nt][3]+by);
        }
    }
}

// ---------------- init / hk ----------------
__global__ void init_kernel() { if (threadIdx.x == 0) g_kstab = 0xFF800000u; }

__global__ __launch_bounds__(256) void hk_kernel() {
    int gid = blockIdx.x * 256 + threadIdx.x;
    int b = gid / (H_*L_), rem = gid % (H_*L_), h = rem / L_, l = rem % L_;
    const float4* row = (const float4*)(g_Kp + (size_t)(b*L_ + l)*D_ + h*DH_);
    float s = 0.f;
    #pragma unroll
    for (int t = 0; t < 16; ++t) {
        float4 v = row[t];
        s = fmaf(v.x,v.x,s); s = fmaf(v.y,v.y,s); s = fmaf(v.z,v.z,s); s = fmaf(v.w,v.w,s);
    }
    float hk = -0.5f * SCALE2 * s;
    g_hk[gid] = hk;
    float m = hk;
    #pragma unroll
    for (int o = 16; o > 0; o >>= 1) m = fmaxf(m, __shfl_xor_sync(0xffffffffu, m, o));
    __shared__ float wmax[8];
    if ((threadIdx.x & 31) == 0) wmax[threadIdx.x >> 5] = m;
    __syncthreads();
    if (threadIdx.x == 0) {
        float bm = wmax[0];
        #pragma unroll
        for (int w = 1; w < 8; ++w) bm = fmaxf(bm, wmax[w]);
        atomicMin(&g_kstab, __float_as_uint(bm));
    }
}

// ================= fused kv kernel: proj_k + exp + k'^T @ v_aug =================
#define KST 296
#define KW_WFH 0
#define KW_WFL 41472
#define KW_XH  82944
#define KW_XL  92160
#define KW_KH  101376
#define KW_KL  139264
#define KW_VH  177152
#define KW_VL  186368
#define KW_HK  195584
#define KW_MS  195840
#define KW_SMEM 196096

__global__ __launch_bounds__(288, 1) void kv_mma(const float* __restrict__ Wf,
                                                 const float* __restrict__ mask) {
    extern __shared__ char sm[];
    const uint32_t sb = smem_u32(sm);
    const int tid = threadIdx.x, lane = tid & 31, w = tid >> 5;   // 9 warps
    const int split = blockIdx.x, bh = blockIdx.y;
    const int b = bh / H_, h = bh % H_;
    const int arow = lane & 15, acolsel = (lane >> 4) << 3;
    const int brow = (lane & 7) + ((lane >> 4) << 3), bcolsel = ((lane >> 3) & 1) << 3;

    // stage Wf [288][72] hi/lo (rows >=266 and cols >=64 zero)
    for (int i = tid; i < 288*18; i += 288) {
        int r = i / 18, u = i % 18;
        float4 v = make_float4(0.f,0.f,0.f,0.f);
        if (r < 266 && u < 16) v = *(const float4*)(Wf + r*64 + u*4);
        uint32_t h01,h23,l01,l23; cvt_split(v,h01,h23,l01,l23);
        *(uint2*)(sm + KW_WFH + (r*72 + u*4)*2) = make_uint2(h01,h23);
        *(uint2*)(sm + KW_WFL + (r*72 + u*4)*2) = make_uint2(l01,l23);
    }
    float kstab = __uint_as_float(g_kstab);

    float acc[2][9][4];
    #pragma unroll
    for (int t = 0; t < 2; ++t)
        #pragma unroll
        for (int n = 0; n < 9; ++n)
            #pragma unroll
            for (int k = 0; k < 4; ++k) acc[t][n][k] = 0.f;

    for (int c = 0; c < 8; ++c) {
        int lb = split*512 + c*64;
        __syncthreads();
        // K chunk (scaled) -> XH/XL
        for (int i = tid; i < 64*16; i += 288) {
            int r = i >> 4, u = i & 15;
            float4 v = *(const float4*)(g_Kp + (size_t)(b*L_+lb+r)*D_ + h*64 + u*4);
            v.x*=SCALE; v.y*=SCALE; v.z*=SCALE; v.w*=SCALE;
            uint32_t h01,h23,l01,l23; cvt_split(v,h01,h23,l01,l23);
            *(uint2*)(sm + KW_XH + (r*72 + u*4)*2) = make_uint2(h01,h23);
            *(uint2*)(sm + KW_XL + (r*72 + u*4)*2) = make_uint2(l01,l23);
        }
        // V chunk -> VH/VL
        for (int i = tid; i < 64*18; i += 288) {
            int r = i / 18, u = i % 18;
            float4 v;
            if (u < 16) v = *(const float4*)(g_Vp + (size_t)(b*L_+lb+r)*D_ + h*64 + u*4);
            else if (u == 16) v = make_float4(1.f,0.f,0.f,0.f);
            else v = make_float4(0.f,0.f,0.f,0.f);
            uint32_t h01,h23,l01,l23; cvt_split(v,h01,h23,l01,l23);
            *(uint2*)(sm + KW_VH + (r*72 + u*4)*2) = make_uint2(h01,h23);
            *(uint2*)(sm + KW_VL + (r*72 + u*4)*2) = make_uint2(l01,l23);
        }
        if (tid < 64) {
            ((float*)(sm + KW_HK))[tid] = g_hk[(size_t)bh*L_ + lb + tid] - kstab;
            ((float*)(sm + KW_MS))[tid] = mask[b*L_ + lb + tid];
        }
        __syncthreads();
        // proj mma + epilogue, per l-tile to cap registers
        const int r0 = lane >> 2, cb2 = (lane & 3)*2;
        #pragma unroll
        for (int lt = 0; lt < 4; ++lt) {
            float pa[4][4];
            #pragma unroll
            for (int n = 0; n < 4; ++n)
                #pragma unroll
                for (int k = 0; k < 4; ++k) pa[n][k] = 0.f;
            #pragma unroll
            for (int ks = 0; ks < 4; ++ks) {
                uint32_t ah[4], al[4];
                uint32_t aoff = (uint32_t)(((lt*16 + arow)*72 + ks*16 + acolsel)*2);
                LDSM_X4(ah[0],ah[1],ah[2],ah[3], sb + KW_XH + aoff);
                LDSM_X4(al[0],al[1],al[2],al[3], sb + KW_XL + aoff);
                #pragma unroll
                for (int g = 0; g < 2; ++g) {
                    uint32_t boff = (uint32_t)((((2*w+g)*16 + brow)*72 + ks*16 + bcolsel)*2);
                    uint32_t bh_[4], bl_[4];
                    LDSM_X4(bh_[0],bh_[1],bh_[2],bh_[3], sb + KW_WFH + boff);
                    LDSM_X4(bl_[0],bl_[1],bl_[2],bl_[3], sb + KW_WFL + boff);
                    #pragma unroll
                    for (int half = 0; half < 2; ++half) {
                        int nt = 2*g + half;
                        MMA_BF16(pa[nt], ah, bh_[half*2], bh_[half*2+1]);
                        MMA_BF16(pa[nt], ah, bl_[half*2], bl_[half*2+1]);
                        MMA_BF16(pa[nt], al, bh_[half*2], bh_[half*2+1]);
                    }
                }
            }
            int ra = lt*16 + r0, rb = ra + 8;
            float ha = ((float*)(sm + KW_HK))[ra], hb = ((float*)(sm + KW_HK))[rb];
            float ma = ((float*)(sm + KW_MS))[ra], mb = ((float*)(sm + KW_MS))[rb];
            #pragma unroll
            for (int nt = 0; nt < 4; ++nt) {
                int c0 = 32*w + nt*8 + cb2;
                float e0=0.f,e1=0.f,e2=0.f,e3=0.f;
                if (c0 < M_)   { e0 = NC*(__expf(pa[nt][0]+ha)+KEPS)*ma; e2 = NC*(__expf(pa[nt][2]+hb)+KEPS)*mb; }
                if (c0+1 < M_) { e1 = NC*(__expf(pa[nt][1]+ha)+KEPS)*ma; e3 = NC*(__expf(pa[nt][3]+hb)+KEPS)*mb; }
                uint32_t hh, ll;
                cvt_split2(e0, e1, hh, ll);
                *(uint32_t*)(sm + KW_KH + (ra*KST + c0)*2) = hh;
                *(uint32_t*)(sm + KW_KL + (ra*KST + c0)*2) = ll;
                cvt_split2(e2, e3, hh, ll);
                *(uint32_t*)(sm + KW_KH + (rb*KST + c0)*2) = hh;
                *(uint32_t*)(sm + KW_KL + (rb*KST + c0)*2) = ll;
            }
        }
        __syncthreads();
        // kv mma: acc[m, d] += k'^T @ v_aug
        #pragma unroll
        for (int ks = 0; ks < 4; ++ks) {
            uint32_t ah2[2][4], al2[2][4];
            #pragma unroll
            for (int t = 0; t < 2; ++t) {
                uint32_t off = (uint32_t)(((ks*16 + brow)*KST + (2*w + t)*16 + bcolsel)*2);
                LDSM_X4T(ah2[t][0],ah2[t][1],ah2[t][2],ah2[t][3], sb + KW_KH + off);
                LDSM_X4T(al2[t][0],al2[t][1],al2[t][2],al2[t][3], sb + KW_KL + off);
            }
            uint32_t bh4[4][4], bl4[4][4], bh2[2], bl2[2];
            #pragma unroll
            for (int g = 0; g < 4; ++g) {
                uint32_t off = (uint32_t)(((ks*16 + arow)*72 + g*16 + acolsel)*2);
                LDSM_X4T(bh4[g][0],bh4[g][1],bh4[g][2],bh4[g][3], sb + KW_VH + off);
                LDSM_X4T(bl4[g][0],bl4[g][1],bl4[g][2],bl4[g][3], sb + KW_VL + off);
            }
            uint32_t off2 = (uint32_t)(((ks*16 + (lane & 15))*72 + 64)*2);
            LDSM_X2T(bh2[0], bh2[1], sb + KW_VH + off2);
            LDSM_X2T(bl2[0], bl2[1], sb + KW_VL + off2);
            #pragma unroll
            for (int t = 0; t < 2; ++t)
                #pragma unroll
                for (int nt = 0; nt < 9; ++nt) {
                    uint32_t p0 = (nt < 8) ? bh4[nt>>1][(nt&1)*2]   : bh2[0];
                    uint32_t p1 = (nt < 8) ? bh4[nt>>1][(nt&1)*2+1] : bh2[1];
                    uint32_t q0 = (nt < 8) ? bl4[nt>>1][(nt&1)*2]   : bl2[0];
                    uint32_t q1 = (nt < 8) ? bl4[nt>>1][(nt&1)*2+1] : bl2[1];
                    MMA_BF16(acc[t][nt], ah2[t], p0, p1);
                    MMA_BF16(acc[t][nt], ah2[t], q0, q1);
                    MMA_BF16(acc[t][nt], al2[t], p0, p1);
                }
        }
    }
    float* base = g_kvpart + (size_t)(split*BH + bh)*KVROW*KVCOL;
    #pragma unroll
    for (int t = 0; t < 2; ++t) {
        int m0 = w*32 + t*16;
        if (m0 < KVROW) {
            int r0 = m0 + (lane >> 2);
            #pragma unroll
            for (int nt = 0; nt < 9; ++nt) {
                int c0 = nt*8 + (lane & 3)*2;
                *(float2*)(base + (size_t)r0*KVCOL + c0)     = make_float2(acc[t][nt][0], acc[t][nt][1]);
                *(float2*)(base + (size_t)(r0+8)*KVCOL + c0) = make_float2(acc[t][nt][2], acc[t][nt][3]);
            }
        }
    }
}

__global__ void kv_reduce() {
    int idx = blockIdx.x * 256 + threadIdx.x;
    if (idx < KVSZ2) {
        float s = 0.f;
        #pragma unroll
        for (int p = 0; p < SPLIT; ++p) s += g_kvpart[(size_t)p*KVSZ2 + idx];
        g_kv[idx] = s;
    }
}

// ================= fused out kernel: proj_q + exp + q' @ kv + denom =================
#define OW_KVH 0
#define OW_KVL 41472
#define OW_XH  82944
#define OW_XL  101376
#define OW_QH  119808
#define OW_QL  130048
#define OW_WFH 140288
#define OW_WFL 144896
#define OW_SMEM 149504

__global__ __launch_bounds__(256, 1) void out_mma(const float* __restrict__ Wf) {
    extern __shared__ char sm[];
    const uint32_t sb = smem_u32(sm);
    const int tid = threadIdx.x, lane = tid & 31, w = tid >> 5;   // 8 warps
    const int h = blockIdx.y, b = blockIdx.z, bh = b*H_ + h;
    const int l0 = blockIdx.x * 128;
    const int arow = lane & 15, acolsel = (lane >> 4) << 3;
    const int brow = (lane & 7) + ((lane >> 4) << 3), bcolsel = ((lane >> 3) & 1) << 3;

    // zero kv buffers (covers rows 272..287 and cols 65..71)
    for (int i = tid; i < 82944/4; i += 256) ((uint32_t*)sm)[i] = 0;
    __syncthreads();
    for (int i = tid; i < KVROW*18; i += 256) {
        int r = i / 18, u = i % 18;
        float4 v = *(const float4*)(g_kv + ((size_t)bh*KVROW + r)*KVCOL + u*4);
        uint32_t h01,h23,l01,l23; cvt_split(v,h01,h23,l01,l23);
        *(uint2*)(sm + OW_KVH + (r*72 + u*4)*2) = make_uint2(h01,h23);
        *(uint2*)(sm + OW_KVL + (r*72 + u*4)*2) = make_uint2(l01,l23);
    }
    // Q block (scaled) -> XH/XL [128][72]
    for (int i = tid; i < 128*16; i += 256) {
        int r = i >> 4, u = i & 15;
        float4 v = *(const float4*)(g_Qp + (size_t)(b*L_+l0+r)*D_ + h*64 + u*4);
        v.x*=SCALE; v.y*=SCALE; v.z*=SCALE; v.w*=SCALE;
        uint32_t h01,h23,l01,l23; cvt_split(v,h01,h23,l01,l23);
        *(uint2*)(sm + OW_XH + (r*72 + u*4)*2) = make_uint2(h01,h23);
        *(uint2*)(sm + OW_XL + (r*72 + u*4)*2) = make_uint2(l01,l23);
    }

    float acc[9][4];
    #pragma unroll
    for (int n = 0; n < 9; ++n)
        #pragma unroll
        for (int k = 0; k < 4; ++k) acc[n][k] = 0.f;

    const int r0 = lane >> 2, cb2 = (lane & 3)*2;

    for (int mc = 0; mc < 9; ++mc) {
        __syncthreads();   // first iter: covers fills; later: protects WFH/QH
        // Wf chunk rows mc*32..+31 (L2-resident re-reads)
        for (int i = tid; i < 32*18; i += 256) {
            int r = i / 18, u = i % 18;
            int gr = mc*32 + r;
            float4 v = make_float4(0.f,0.f,0.f,0.f);
            if (gr < 266 && u < 16) v = *(const float4*)(Wf + gr*64 + u*4);
            uint32_t h01,h23,l01,l23; cvt_split(v,h01,h23,l01,l23);
            *(uint2*)(sm + OW_WFH + (r*72 + u*4)*2) = make_uint2(h01,h23);
            *(uint2*)(sm + OW_WFL + (r*72 + u*4)*2) = make_uint2(l01,l23);
        }
        __syncthreads();
        // proj mma: warp w = rows w*16..w*16+15, 32 cols
        float pa[4][4];
        #pragma unroll
        for (int n = 0; n < 4; ++n)
            #pragma unroll
            for (int k = 0; k < 4; ++k) pa[n][k] = 0.f;
        #pragma unroll
        for (int ks = 0; ks < 4; ++ks) {
            uint32_t ah[4], al[4];
            uint32_t aoff = (uint32_t)(((w*16 + arow)*72 + ks*16 + acolsel)*2);
            LDSM_X4(ah[0],ah[1],ah[2],ah[3], sb + OW_XH + aoff);
            LDSM_X4(al[0],al[1],al[2],al[3], sb + OW_XL + aoff);
            #pragma unroll
            for (int g = 0; g < 2; ++g) {
                uint32_t boff = (uint32_t)(((g*16 + brow)*72 + ks*16 + bcolsel)*2);
                uint32_t bh_[4], bl_[4];
                LDSM_X4(bh_[0],bh_[1],bh_[2],bh_[3], sb + OW_WFH + boff);
                LDSM_X4(bl_[0],bl_[1],bl_[2],bl_[3], sb + OW_WFL + boff);
                #pragma unroll
                for (int half = 0; half < 2; ++half) {
                    int nt = 2*g + half;
                    MMA_BF16(pa[nt], ah, bh_[half*2], bh_[half*2+1]);
                    MMA_BF16(pa[nt], ah, bl_[half*2], bl_[half*2+1]);
                    MMA_BF16(pa[nt], al, bh_[half*2], bh_[half*2+1]);
                }
            }
        }
        // epilogue: q' chunk -> QH/QL [128][40]
        {
            int ra = w*16 + r0, rb = ra + 8;
            #pragma unroll
            for (int nt = 0; nt < 4; ++nt) {
                int lc = nt*8 + cb2;
                int gc = mc*32 + lc;
                float e0=0.f,e1=0.f,e2=0.f,e3=0.f;
                if (gc < M_)   { e0 = NC*(__expf(pa[nt][0])+KEPS); e2 = NC*(__expf(pa[nt][2])+KEPS); }
                if (gc+1 < M_) { e1 = NC*(__expf(pa[nt][1])+KEPS); e3 = NC*(__expf(pa[nt][3])+KEPS); }
                uint32_t hh, ll;
                cvt_split2(e0, e1, hh, ll);
                *(uint32_t*)(sm + OW_QH + (ra*40 + lc)*2) = hh;
                *(uint32_t*)(sm + OW_QL + (ra*40 + lc)*2) = ll;
                cvt_split2(e2, e3, hh, ll);
                *(uint32_t*)(sm + OW_QH + (rb*40 + lc)*2) = hh;
                *(uint32_t*)(sm + OW_QL + (rb*40 + lc)*2) = ll;
            }
        }
        __syncthreads();
        // out mma over this 32-wide k range
        #pragma unroll
        for (int ks = 0; ks < 2; ++ks) {
            int gk = mc*32 + ks*16;
            uint32_t ah[4], al[4];
            uint32_t aoff = (uint32_t)(((w*16 + arow)*40 + ks*16 + acolsel)*2);
            LDSM_X4(ah[0],ah[1],ah[2],ah[3], sb + OW_QH + aoff);
            LDSM_X4(al[0],al[1],al[2],al[3], sb + OW_QL + aoff);
            uint32_t bh4[4][4], bl4[4][4], bh2[2], bl2[2];
            #pragma unroll
            for (int g = 0; g < 4; ++g) {
                uint32_t off = (uint32_t)(((gk + arow)*72 + g*16 + acolsel)*2);
                LDSM_X4T(bh4[g][0],bh4[g][1],bh4[g][2],bh4[g][3], sb + OW_KVH + off);
                LDSM_X4T(bl4[g][0],bl4[g][1],bl4[g][2],bl4[g][3], sb + OW_KVL + off);
            }
            uint32_t off2 = (uint32_t)(((gk + (lane & 15))*72 + 64)*2);
            LDSM_X2T(bh2[0], bh2[1], sb + OW_KVH + off2);
            LDSM_X2T(bl2[0], bl2[1], sb + OW_KVL + off2);
            #pragma unroll
            for (int nt = 0; nt < 9; ++nt) {
                uint32_t p0 = (nt < 8) ? bh4[nt>>1][(nt&1)*2]   : bh2[0];
                uint32_t p1 = (nt < 8) ? bh4[nt>>1][(nt&1)*2+1] : bh2[1];
                uint32_t q0 = (nt < 8) ? bl4[nt>>1][(nt&1)*2]   : bl2[0];
                uint32_t q1 = (nt < 8) ? bl4[nt>>1][(nt&1)*2+1] : bl2[1];
                MMA_BF16(acc[nt], ah, p0, p1);
                MMA_BF16(acc[nt], ah, q0, q1);
                MMA_BF16(acc[nt], al, p0, p1);
            }
        }
    }
    float den0 = __shfl_sync(0xffffffffu, acc[8][0], lane & ~3);
    float den1 = __shfl_sync(0xffffffffu, acc[8][2], lane & ~3);
    if (fabsf(den0) <= NSTAB) den0 += 2.f*NSTAB;
    if (fabsf(den1) <= NSTAB) den1 += 2.f*NSTAB;
    float inv0 = 1.f/den0, inv1 = 1.f/den1;
    int rr = w*16 + r0;
    size_t gl0 = (size_t)(b*L_ + l0 + rr), gl1 = gl0 + 8;
    #pragma unroll
    for (int nt = 0; nt < 8; ++nt) {
        int c0 = nt*8 + cb2;
        *(float2*)(g_ctx + gl0*D_ + h*64 + c0) = make_float2(acc[nt][0]*inv0, acc[nt][1]*inv0);
        *(float2*)(g_ctx + gl1*D_ + h*64 + c0) = make_float2(acc[nt][2]*inv1, acc[nt][3]*inv1);
    }
}

// ---------------- launch ----------------
extern "C" void kernel_launch(void* const* d_in, const int* in_sizes, int n_in,
                              void* d_out, int out_size) {
    const float* query = (const float*)d_in[0];
    const float* key   = (const float*)d_in[1];
    const float* value = (const float*)d_in[2];
    const float* mask  = (const float*)d_in[3];
    const float* Wq = (const float*)d_in[4];
    const float* bq = (const float*)d_in[5];
    const float* Wk = (const float*)d_in[6];
    const float* bk = (const float*)d_in[7];
    const float* Wv = (const float*)d_in[8];
    const float* bv = (const float*)d_in[9];
    const float* Wo = (const float*)d_in[10];
    const float* bo = (const float*)d_in[11];
    const float* Wf = (const float*)d_in[12];

    float *Qp, *Kp, *Vp, *ctx;
    cudaGetSymbolAddress((void**)&Qp,  g_Qp);
    cudaGetSymbolAddress((void**)&Kp,  g_Kp);
    cudaGetSymbolAddress((void**)&Vp,  g_Vp);
    cudaGetSymbolAddress((void**)&ctx, g_ctx);

    cudaFuncSetAttribute(gemm_mma, cudaFuncAttributeMaxDynamicSharedMemorySize, G_SMEM);
    cudaFuncSetAttribute(kv_mma,   cudaFuncAttributeMaxDynamicSharedMemorySize, KW_SMEM);
    cudaFuncSetAttribute(out_mma,  cudaFuncAttributeMaxDynamicSharedMemorySize, OW_SMEM);

    init_kernel<<<1, 32>>>();

    dim3 gg(D_/128, BL/128);
    gemm_mma<<<gg, 256, G_SMEM>>>(query, Wq, bq, Qp);
    gemm_mma<<<gg, 256, G_SMEM>>>(key,   Wk, bk, Kp);
    gemm_mma<<<gg, 256, G_SMEM>>>(value, Wv, bv, Vp);

    hk_kernel<<<(BH*L_)/256, 256>>>();

    kv_mma<<<dim3(SPLIT, BH), 288, KW_SMEM>>>(Wf, mask);
    kv_reduce<<<(KVSZ2 + 255)/256, 256>>>();

    out_mma<<<dim3(L_/128, H_, B_), 256, OW_SMEM>>>(Wf);

    gemm_mma<<<gg, 256, G_SMEM>>>(ctx, Wo, bo, (float*)d_out);
}